// round 10
// baseline (speedup 1.0000x reference)
#include <cuda_runtime.h>
#include <cuda_bf16.h>
#include <cstdint>
#include <math.h>

using std::uint32_t;

// ---------------- problem constants ----------------
#define S_LEN 2048
#define HID   2048
#define NH    16
#define HD    128
#define NQKV  6144   // 3 * HID
#define ROT   32

typedef __nv_bfloat16 bf16;

// ---------------- scratch (device globals; no runtime alloc) ----------------
__device__ float g_mixed[(size_t)S_LEN * NQKV];

__device__ bf16 g_ah[(size_t)S_LEN * HID];
__device__ bf16 g_al[(size_t)S_LEN * HID];
__device__ bf16 g_bh[(size_t)HID * NQKV];
__device__ bf16 g_bl[(size_t)HID * NQKV];
__device__ bf16 g_wh[(size_t)HID * HID];
__device__ bf16 g_wl[(size_t)HID * HID];
__device__ bf16 g_ch[(size_t)S_LEN * HID];
__device__ bf16 g_cl[(size_t)S_LEN * HID];

__device__ bf16 g_qh[(size_t)NH * S_LEN * HD];
__device__ bf16 g_ql[(size_t)NH * S_LEN * HD];
__device__ bf16 g_kh[(size_t)NH * S_LEN * HD];
__device__ bf16 g_kl[(size_t)NH * S_LEN * HD];
__device__ bf16 g_vh[(size_t)NH * S_LEN * HD];
__device__ bf16 g_vl[(size_t)NH * S_LEN * HD];

// ---------------- common PTX helpers ----------------
__device__ __forceinline__ void cp_async16(void* smem_dst, const void* gmem_src) {
    uint32_t s = (uint32_t)__cvta_generic_to_shared(smem_dst);
    asm volatile("cp.async.cg.shared.global [%0], [%1], 16;\n" :: "r"(s), "l"(gmem_src));
}
__device__ __forceinline__ void cp_commit() {
    asm volatile("cp.async.commit_group;\n");
}
template <int N>
__device__ __forceinline__ void cp_wait() {
    asm volatile("cp.async.wait_group %0;\n" :: "n"(N));
}

__device__ __forceinline__ void mma16816(float* c, const uint32_t* a, const uint32_t* b) {
    asm volatile(
        "mma.sync.aligned.m16n8k16.row.col.f32.bf16.bf16.f32 "
        "{%0,%1,%2,%3}, {%4,%5,%6,%7}, {%8,%9}, {%0,%1,%2,%3};\n"
        : "+f"(c[0]), "+f"(c[1]), "+f"(c[2]), "+f"(c[3])
        : "r"(a[0]), "r"(a[1]), "r"(a[2]), "r"(a[3]), "r"(b[0]), "r"(b[1]));
}

__device__ __forceinline__ void ldmx4(uint32_t* r, const void* p) {
    uint32_t a = (uint32_t)__cvta_generic_to_shared(p);
    asm volatile("ldmatrix.sync.aligned.m8n8.x4.shared.b16 {%0,%1,%2,%3}, [%4];"
                 : "=r"(r[0]), "=r"(r[1]), "=r"(r[2]), "=r"(r[3]) : "r"(a));
}
__device__ __forceinline__ void ldmx4t(uint32_t* r, const void* p) {
    uint32_t a = (uint32_t)__cvta_generic_to_shared(p);
    asm volatile("ldmatrix.sync.aligned.m8n8.x4.trans.shared.b16 {%0,%1,%2,%3}, [%4];"
                 : "=r"(r[0]), "=r"(r[1]), "=r"(r[2]), "=r"(r[3]) : "r"(a));
}

// ---------------- fp32 -> bf16 hi/lo split ----------------
__global__ __launch_bounds__(256) void split_bf16_kernel(
    const float* __restrict__ x, bf16* __restrict__ hi, bf16* __restrict__ lo, int n4)
{
    int i = blockIdx.x * blockDim.x + threadIdx.x;
    if (i >= n4) return;
    float4 v = reinterpret_cast<const float4*>(x)[i];
    bf16 h0 = __float2bfloat16(v.x);
    bf16 h1 = __float2bfloat16(v.y);
    bf16 h2 = __float2bfloat16(v.z);
    bf16 h3 = __float2bfloat16(v.w);
    bf16 l0 = __float2bfloat16(v.x - __bfloat162float(h0));
    bf16 l1 = __float2bfloat16(v.y - __bfloat162float(h1));
    bf16 l2 = __float2bfloat16(v.z - __bfloat162float(h2));
    bf16 l3 = __float2bfloat16(v.w - __bfloat162float(h3));
    __nv_bfloat162* hp = reinterpret_cast<__nv_bfloat162*>(hi);
    __nv_bfloat162* lp = reinterpret_cast<__nv_bfloat162*>(lo);
    hp[2 * i]     = __nv_bfloat162(h0, h1);
    hp[2 * i + 1] = __nv_bfloat162(h2, h3);
    lp[2 * i]     = __nv_bfloat162(l0, l1);
    lp[2 * i + 1] = __nv_bfloat162(l2, l3);
}

// ---------------- HMMA GEMM (bf16x3, fp32 accum) ----------------
// 128x256 block tile, BK=32, 256 threads (8 warps 2x4), warp tile 64x64.
// 3-stage cp.async ring, one __syncthreads per stage.
#define GBK 32
#define SA     40                    // 32 + 8 pad
#define SB     264                   // 256 + 8 pad
#define OAH    0
#define OAL    (128 * SA)            // 5120
#define OBH    (2 * 128 * SA)        // 10240
#define OBL    (OBH + GBK * SB)      // 18688
#define BUFSZ  (OBL + GBK * SB)      // 27136 bf16 = 54272 B
#define GEMM_SMEM (3 * BUFSZ * 2)    // 162816 B

__global__ __launch_bounds__(256, 1) void mma_gemm_bf16x3(
    const bf16* __restrict__ Ah, const bf16* __restrict__ Al,
    const bf16* __restrict__ Bh, const bf16* __restrict__ Bl,
    const float* __restrict__ bias, float* __restrict__ C,
    int M, int N, int K)
{
    extern __shared__ __align__(16) unsigned char smraw[];
    bf16* sm = reinterpret_cast<bf16*>(smraw);

    const int bx = blockIdx.x;     // N tile (256)
    const int by = blockIdx.y;     // M tile (128)
    const int tid = threadIdx.x;
    const int warp = tid >> 5;
    const int lane = tid & 31;
    const int warp_m = warp >> 2;      // 0..1  (64 rows)
    const int warp_n = warp & 3;       // 0..3  (64 cols)
    const int g  = lane >> 2;
    const int tg = lane & 3;

    const int nst = K / GBK;           // 64

    float acc[4][8][4];
    #pragma unroll
    for (int i = 0; i < 4; i++)
        #pragma unroll
        for (int j = 0; j < 8; j++)
            #pragma unroll
            for (int x = 0; x < 4; x++) acc[i][j][x] = 0.0f;

    auto issue = [&](int s) {
        const int k0 = s * GBK;
        bf16* buf = sm + (s % 3) * BUFSZ;
        // A: 128 rows x 4 chunks = 512 chunks per array, 2/thread each
        #pragma unroll
        for (int p = 0; p < 2; p++) {
            int q = tid + p * 256;
            int r = q >> 2, c = q & 3;
            size_t ga = (size_t)(by * 128 + r) * K + k0 + c * 8;
            int sa = r * SA + c * 8;
            cp_async16(buf + OAH + sa, Ah + ga);
            cp_async16(buf + OAL + sa, Al + ga);
        }
        // B: 32 rows x 32 chunks = 1024 chunks per array, 4/thread each
        #pragma unroll
        for (int p = 0; p < 4; p++) {
            int q = tid + p * 256;
            int r = q >> 5, c = q & 31;
            size_t gb = (size_t)(k0 + r) * N + bx * 256 + c * 8;
            int sb = r * SB + c * 8;
            cp_async16(buf + OBH + sb, Bh + gb);
            cp_async16(buf + OBL + sb, Bl + gb);
        }
    };

    issue(0); cp_commit();
    issue(1); cp_commit();

    const int a_row = lane & 15;
    const int a_colh = (lane >> 4) << 3;
    const int b_row = lane & 15;
    const int b_colh = (lane >> 4) << 3;

    for (int s = 0; s < nst; s++) {
        cp_wait<1>();
        __syncthreads();
        if (s + 2 < nst) { issue(s + 2); cp_commit(); }

        const bf16* buf = sm + (s % 3) * BUFSZ;

        #pragma unroll
        for (int ks = 0; ks < GBK; ks += 16) {
            uint32_t ah[4][4], al[4][4];
            #pragma unroll
            for (int i = 0; i < 4; i++) {
                int ra = (warp_m * 64 + i * 16 + a_row) * SA + ks + a_colh;
                ldmx4(ah[i], buf + OAH + ra);
                ldmx4(al[i], buf + OAL + ra);
            }
            #pragma unroll
            for (int jp = 0; jp < 4; jp++) {
                int rb = (ks + b_row) * SB + warp_n * 64 + jp * 16 + b_colh;
                uint32_t th[4], tl[4];
                ldmx4t(th, buf + OBH + rb);
                ldmx4t(tl, buf + OBL + rb);
                uint32_t b0h[2] = {th[0], th[1]}, b1h[2] = {th[2], th[3]};
                uint32_t b0l[2] = {tl[0], tl[1]}, b1l[2] = {tl[2], tl[3]};
                #pragma unroll
                for (int i = 0; i < 4; i++) {
                    mma16816(acc[i][2 * jp],     ah[i], b0h);
                    mma16816(acc[i][2 * jp],     ah[i], b0l);
                    mma16816(acc[i][2 * jp],     al[i], b0h);
                    mma16816(acc[i][2 * jp + 1], ah[i], b1h);
                    mma16816(acc[i][2 * jp + 1], ah[i], b1l);
                    mma16816(acc[i][2 * jp + 1], al[i], b1h);
                }
            }
        }
    }

    #pragma unroll
    for (int i = 0; i < 4; i++) {
        #pragma unroll
        for (int j = 0; j < 8; j++) {
            int row0 = by * 128 + warp_m * 64 + i * 16 + g;
            int col  = bx * 256 + warp_n * 64 + j * 8 + tg * 2;
            float b0 = bias[col], b1 = bias[col + 1];
            float2 v0 = make_float2(acc[i][j][0] + b0, acc[i][j][1] + b1);
            float2 v1 = make_float2(acc[i][j][2] + b0, acc[i][j][3] + b1);
            *reinterpret_cast<float2*>(C + (size_t)row0 * N + col) = v0;
            *reinterpret_cast<float2*>(C + (size_t)(row0 + 8) * N + col) = v1;
        }
    }
}

// ---------------- RoPE + scatter + bf16 hi/lo split ----------------
__global__ __launch_bounds__(128) void qkv_rope_split_kernel(
    const float* __restrict__ mixed,
    bf16* __restrict__ Qh, bf16* __restrict__ Ql,
    bf16* __restrict__ Kh, bf16* __restrict__ Kl,
    bf16* __restrict__ Vh, bf16* __restrict__ Vl)
{
    const int t = blockIdx.x;
    const int h = blockIdx.y;
    const int d = threadIdx.x;

    const float* base = mixed + (size_t)t * NQKV + h * (3 * HD);
    float q = base[d];
    float k = base[HD + d];
    float v = base[2 * HD + d];

    if (d < ROT) {
        const int i = d & 15;
        float inv_freq = 1.0f / powf(10000.0f, (float)(2 * i) * (1.0f / (float)ROT));
        float ang = (float)t * inv_freq;
        float s, c;
        sincosf(ang, &s, &c);
        if (d < 16) {
            q = q * c - base[d + 16] * s;
            k = k * c - base[HD + d + 16] * s;
        } else {
            q = q * c + base[d - 16] * s;
            k = k * c + base[HD + d - 16] * s;
        }
    }

    size_t off = ((size_t)h * S_LEN + t) * HD + d;
    bf16 qhi = __float2bfloat16(q);
    bf16 khi = __float2bfloat16(k);
    bf16 vhi = __float2bfloat16(v);
    Qh[off] = qhi;  Ql[off] = __float2bfloat16(q - __bfloat162float(qhi));
    Kh[off] = khi;  Kl[off] = __float2bfloat16(k - __bfloat162float(khi));
    Vh[off] = vhi;  Vl[off] = __float2bfloat16(v - __bfloat162float(vhi));
}

// ---------------- HMMA flash attention (bf16x3, causal) ----------------
#define FBM 128
#define FBN 64
#define FSTR 136

#define FQH 0
#define FQL (128 * FSTR)
#define FKV0 (2 * 128 * FSTR)
#define KVARR (64 * FSTR)
#define KVSTG (4 * KVARR)
#define FLASH_SMEM ((FKV0 + 2 * KVSTG) * 2)

__global__ __launch_bounds__(256, 1) void flash_mma_kernel(
    const bf16* __restrict__ Qh, const bf16* __restrict__ Ql,
    const bf16* __restrict__ Kh, const bf16* __restrict__ Kl,
    const bf16* __restrict__ Vh, const bf16* __restrict__ Vl,
    bf16* __restrict__ Ch, bf16* __restrict__ Cl)
{
    extern __shared__ __align__(16) unsigned char fsraw[];
    bf16* fs = reinterpret_cast<bf16*>(fsraw);

    const int h = blockIdx.y;
    const int m_tile = gridDim.x - 1 - blockIdx.x;
    const int m0 = m_tile * FBM;
    const int tid = threadIdx.x;
    const int warp = tid >> 5;
    const int lane = tid & 31;
    const int g  = lane >> 2;
    const int tg = lane & 3;

    const bf16* qhp = Qh + ((size_t)h * S_LEN + m0) * HD;
    const bf16* qlp = Ql + ((size_t)h * S_LEN + m0) * HD;
    const bf16* khp = Kh + (size_t)h * S_LEN * HD;
    const bf16* klp = Kl + (size_t)h * S_LEN * HD;
    const bf16* vhp = Vh + (size_t)h * S_LEN * HD;
    const bf16* vlp = Vl + (size_t)h * S_LEN * HD;

    for (int idx = tid; idx < 2048; idx += 256) {
        int r = idx >> 4, c = (idx & 15) << 3;
        *reinterpret_cast<float4*>(fs + FQH + r * FSTR + c) =
            *reinterpret_cast<const float4*>(qhp + (size_t)r * HD + c);
        *reinterpret_cast<float4*>(fs + FQL + r * FSTR + c) =
            *reinterpret_cast<const float4*>(qlp + (size_t)r * HD + c);
    }

    auto issue_kv = [&](int nt) {
        const int n0 = nt * FBN;
        bf16* buf = fs + FKV0 + (nt & 1) * KVSTG;
        #pragma unroll
        for (int q = tid; q < 1024; q += 256) {
            int r = q >> 4, c = (q & 15) << 3;
            size_t go = (size_t)(n0 + r) * HD + c;
            int so = r * FSTR + c;
            cp_async16(buf + 0 * KVARR + so, khp + go);
            cp_async16(buf + 1 * KVARR + so, klp + go);
            cp_async16(buf + 2 * KVARR + so, vhp + go);
            cp_async16(buf + 3 * KVARR + so, vlp + go);
        }
    };

    float o[16][4];
    #pragma unroll
    for (int j = 0; j < 16; j++)
        #pragma unroll
        for (int x = 0; x < 4; x++) o[j][x] = 0.0f;
    float mrow0 = -1e30f, mrow1 = -1e30f, lrow0 = 0.0f, lrow1 = 0.0f;

    const float scale = 0.08838834764831845f;
    const int row0 = m0 + warp * 16 + g;
    const int row1 = row0 + 8;
    const int wrow_max = m0 + warp * 16 + 15;

    const int a_row = lane & 15;
    const int half8 = (lane >> 4) << 3;
    const int bk_colh = ((lane >> 3) & 1) << 3;

    const int ntiles = m0 / FBN + 2;
    issue_kv(0); cp_commit();

    for (int nt = 0; nt < ntiles; nt++) {
        const int n0 = nt * FBN;
        if (nt + 1 < ntiles) { issue_kv(nt + 1); cp_commit(); cp_wait<1>(); }
        else                 { cp_wait<0>(); }
        __syncthreads();

        if (n0 <= wrow_max) {
            const bf16* kvb = fs + FKV0 + (nt & 1) * KVSTG;
            const bf16* kh_s = kvb;
            const bf16* kl_s = kvb + KVARR;
            const bf16* vh_s = kvb + 2 * KVARR;
            const bf16* vl_s = kvb + 3 * KVARR;

            float sacc[8][4];
            #pragma unroll
            for (int j = 0; j < 8; j++)
                #pragma unroll
                for (int x = 0; x < 4; x++) sacc[j][x] = 0.0f;

            #pragma unroll
            for (int ks = 0; ks < 8; ks++) {
                const int k = ks * 16;
                uint32_t aH[4], aL[4];
                {
                    int ra = (warp * 16 + a_row) * FSTR + k + half8;
                    ldmx4(aH, fs + FQH + ra);
                    ldmx4(aL, fs + FQL + ra);
                }
                #pragma unroll
                for (int jp = 0; jp < 4; jp++) {
                    int rb = (jp * 16 + half8 + (lane & 7)) * FSTR + k + bk_colh;
                    uint32_t bH[4], bL[4];
                    ldmx4(bH, kh_s + rb);
                    ldmx4(bL, kl_s + rb);
                    uint32_t b0h[2] = {bH[0], bH[1]}, b1h[2] = {bH[2], bH[3]};
                    uint32_t b0l[2] = {bL[0], bL[1]}, b1l[2] = {bL[2], bL[3]};
                    mma16816(sacc[2 * jp],     aH, b0h);
                    mma16816(sacc[2 * jp],     aH, b0l);
                    mma16816(sacc[2 * jp],     aL, b0h);
                    mma16816(sacc[2 * jp + 1], aH, b1h);
                    mma16816(sacc[2 * jp + 1], aH, b1l);
                    mma16816(sacc[2 * jp + 1], aL, b1h);
                }
            }

            const bool boundary = (n0 + FBN - 1 > m0);
            #pragma unroll
            for (int j = 0; j < 8; j++) {
                int c0 = n0 + j * 8 + 2 * tg;
                if (boundary) {
                    sacc[j][0] = (c0     > row0) ? -1e30f : sacc[j][0] * scale;
                    sacc[j][1] = (c0 + 1 > row0) ? -1e30f : sacc[j][1] * scale;
                    sacc[j][2] = (c0     > row1) ? -1e30f : sacc[j][2] * scale;
                    sacc[j][3] = (c0 + 1 > row1) ? -1e30f : sacc[j][3] * scale;
                } else {
                    sacc[j][0] *= scale; sacc[j][1] *= scale;
                    sacc[j][2] *= scale; sacc[j][3] *= scale;
                }
            }

            float mx0 = -1e30f, mx1 = -1e30f;
            #pragma unroll
            for (int j = 0; j < 8; j++) {
                mx0 = fmaxf(mx0, fmaxf(sacc[j][0], sacc[j][1]));
                mx1 = fmaxf(mx1, fmaxf(sacc[j][2], sacc[j][3]));
            }
            mx0 = fmaxf(mx0, __shfl_xor_sync(0xffffffffu, mx0, 1));
            mx0 = fmaxf(mx0, __shfl_xor_sync(0xffffffffu, mx0, 2));
            mx1 = fmaxf(mx1, __shfl_xor_sync(0xffffffffu, mx1, 1));
            mx1 = fmaxf(mx1, __shfl_xor_sync(0xffffffffu, mx1, 2));

            float mn0 = fmaxf(mrow0, mx0);
            float mn1 = fmaxf(mrow1, mx1);
            float alpha0 = __expf(mrow0 - mn0);
            float alpha1 = __expf(mrow1 - mn1);
            mrow0 = mn0; mrow1 = mn1;

            float sum0 = 0.0f, sum1 = 0.0f;
            #pragma unroll
            for (int j = 0; j < 8; j++) {
                sacc[j][0] = __expf(sacc[j][0] - mn0);
                sacc[j][1] = __expf(sacc[j][1] - mn0);
                sacc[j][2] = __expf(sacc[j][2] - mn1);
                sacc[j][3] = __expf(sacc[j][3] - mn1);
                sum0 += sacc[j][0] + sacc[j][1];
                sum1 += sacc[j][2] + sacc[j][3];
            }
            sum0 += __shfl_xor_sync(0xffffffffu, sum0, 1);
            sum0 += __shfl_xor_sync(0xffffffffu, sum0, 2);
            sum1 += __shfl_xor_sync(0xffffffffu, sum1, 1);
            sum1 += __shfl_xor_sync(0xffffffffu, sum1, 2);
            lrow0 = lrow0 * alpha0 + sum0;
            lrow1 = lrow1 * alpha1 + sum1;

            #pragma unroll
            for (int j = 0; j < 16; j++) {
                o[j][0] *= alpha0; o[j][1] *= alpha0;
                o[j][2] *= alpha1; o[j][3] *= alpha1;
            }

            #pragma unroll
            for (int kk = 0; kk < 4; kk++) {
                uint32_t paH[4], paL[4];
                #pragma unroll
                for (int half = 0; half < 2; half++) {
                    const float* sv = sacc[2 * kk + half];
                    __nv_bfloat162 h0 = __floats2bfloat162_rn(sv[0], sv[1]);
                    __nv_bfloat162 h1 = __floats2bfloat162_rn(sv[2], sv[3]);
                    __nv_bfloat162 l0 = __floats2bfloat162_rn(
                        sv[0] - __bfloat162float(h0.x), sv[1] - __bfloat162float(h0.y));
                    __nv_bfloat162 l1 = __floats2bfloat162_rn(
                        sv[2] - __bfloat162float(h1.x), sv[3] - __bfloat162float(h1.y));
                    paH[2 * half]     = *reinterpret_cast<uint32_t*>(&h0);
                    paH[2 * half + 1] = *reinterpret_cast<uint32_t*>(&h1);
                    paL[2 * half]     = *reinterpret_cast<uint32_t*>(&l0);
                    paL[2 * half + 1] = *reinterpret_cast<uint32_t*>(&l1);
                }
                #pragma unroll
                for (int jp = 0; jp < 8; jp++) {
                    int rv = (kk * 16 + a_row) * FSTR + jp * 16 + half8;
                    uint32_t vH[4], vL[4];
                    ldmx4t(vH, vh_s + rv);
                    ldmx4t(vL, vl_s + rv);
                    uint32_t v0h[2] = {vH[0], vH[1]}, v1h[2] = {vH[2], vH[3]};
                    uint32_t v0l[2] = {vL[0], vL[1]}, v1l[2] = {vL[2], vL[3]};
                    mma16816(o[2 * jp],     paH, v0h);
                    mma16816(o[2 * jp],     paH, v0l);
                    mma16816(o[2 * jp],     paL, v0h);
                    mma16816(o[2 * jp + 1], paH, v1h);
                    mma16816(o[2 * jp + 1], paH, v1l);
                    mma16816(o[2 * jp + 1], paL, v1h);
                }
            }
        }
        __syncthreads();
    }

    float inv0 = 1.0f / lrow0;
    float inv1 = 1.0f / lrow1;
    #pragma unroll
    for (int jt = 0; jt < 16; jt++) {
        int col = h * HD + jt * 8 + 2 * tg;
        float v00 = o[jt][0] * inv0, v01 = o[jt][1] * inv0;
        float v10 = o[jt][2] * inv1, v11 = o[jt][3] * inv1;
        __nv_bfloat162 h0 = __floats2bfloat162_rn(v00, v01);
        __nv_bfloat162 h1 = __floats2bfloat162_rn(v10, v11);
        __nv_bfloat162 l0 = __floats2bfloat162_rn(
            v00 - __bfloat162float(h0.x), v01 - __bfloat162float(h0.y));
        __nv_bfloat162 l1 = __floats2bfloat162_rn(
            v10 - __bfloat162float(h1.x), v11 - __bfloat162float(h1.y));
        *reinterpret_cast<__nv_bfloat162*>(Ch + (size_t)row0 * HID + col) = h0;
        *reinterpret_cast<__nv_bfloat162*>(Cl + (size_t)row0 * HID + col) = l0;
        *reinterpret_cast<__nv_bfloat162*>(Ch + (size_t)row1 * HID + col) = h1;
        *reinterpret_cast<__nv_bfloat162*>(Cl + (size_t)row1 * HID + col) = l1;
    }
}

// ---------------- launch ----------------
extern "C" void kernel_launch(void* const* d_in, const int* in_sizes, int n_in,
                              void* d_out, int out_size)
{
    const float* hidden  = (const float*)d_in[0];
    const float* W_qkv   = (const float*)d_in[1];
    const float* b_qkv   = (const float*)d_in[2];
    const float* W_dense = (const float*)d_in[3];
    const float* b_dense = (const float*)d_in[4];
    float* out = (float*)d_out;

    float *mixed;
    bf16 *ah, *al, *bh, *bl, *wh, *wl, *ch, *cl;
    bf16 *qh, *ql, *kh, *kl, *vh, *vl;
    cudaGetSymbolAddress((void**)&mixed, g_mixed);
    cudaGetSymbolAddress((void**)&ah,    g_ah);
    cudaGetSymbolAddress((void**)&al,    g_al);
    cudaGetSymbolAddress((void**)&bh,    g_bh);
    cudaGetSymbolAddress((void**)&bl,    g_bl);
    cudaGetSymbolAddress((void**)&wh,    g_wh);
    cudaGetSymbolAddress((void**)&wl,    g_wl);
    cudaGetSymbolAddress((void**)&ch,    g_ch);
    cudaGetSymbolAddress((void**)&cl,    g_cl);
    cudaGetSymbolAddress((void**)&qh,    g_qh);
    cudaGetSymbolAddress((void**)&ql,    g_ql);
    cudaGetSymbolAddress((void**)&kh,    g_kh);
    cudaGetSymbolAddress((void**)&kl,    g_kl);
    cudaGetSymbolAddress((void**)&vh,    g_vh);
    cudaGetSymbolAddress((void**)&vl,    g_vl);

    cudaFuncSetAttribute(mma_gemm_bf16x3,
                         cudaFuncAttributeMaxDynamicSharedMemorySize, GEMM_SMEM);
    cudaFuncSetAttribute(flash_mma_kernel,
                         cudaFuncAttributeMaxDynamicSharedMemorySize, FLASH_SMEM);

    // 0) bf16 hi/lo splits
    {
        int n4 = S_LEN * HID / 4;
        split_bf16_kernel<<<(n4 + 255) / 256, 256>>>(hidden, ah, al, n4);
        int w4 = HID * NQKV / 4;
        split_bf16_kernel<<<(w4 + 255) / 256, 256>>>(W_qkv, bh, bl, w4);
        int d4 = HID * HID / 4;
        split_bf16_kernel<<<(d4 + 255) / 256, 256>>>(W_dense, wh, wl, d4);
    }

    // 1) QKV projection (+bias)
    {
        dim3 grid(NQKV / 256, S_LEN / 128);
        mma_gemm_bf16x3<<<grid, 256, GEMM_SMEM>>>(ah, al, bh, bl, b_qkv, mixed,
                                                  S_LEN, NQKV, HID);
    }

    // 2) RoPE + scatter + split
    qkv_rope_split_kernel<<<dim3(S_LEN, NH), 128>>>(mixed, qh, ql, kh, kl, vh, vl);

    // 3) causal flash attention; writes ctx bf16 hi/lo
    flash_mma_kernel<<<dim3(S_LEN / FBM, NH), 256, FLASH_SMEM>>>(
        qh, ql, kh, kl, vh, vl, ch, cl);

    // 4) dense projection (+bias)
    {
        dim3 grid(HID / 256, S_LEN / 128);
        mma_gemm_bf16x3<<<grid, 256, GEMM_SMEM>>>(ch, cl, wh, wl, b_dense, out,
                                                  S_LEN, HID, HID);
    }
}

// round 11
// speedup vs baseline: 2.0776x; 2.0776x over previous
#include <cuda_runtime.h>
#include <cuda_fp16.h>
#include <cstdint>
#include <math.h>

using std::uint32_t;

// ---------------- problem constants ----------------
#define S_LEN 2048
#define HID   2048
#define NH    16
#define HD    128
#define NQKV  6144   // 3 * HID
#define ROT   32

// ---------------- scratch (device globals; no runtime alloc) ----------------
__device__ float  g_mixed[(size_t)S_LEN * NQKV];

__device__ __half g_a[(size_t)S_LEN * HID];     // hidden fp16
__device__ __half g_b[(size_t)HID * NQKV];      // W_qkv fp16
__device__ __half g_w[(size_t)HID * HID];       // W_dense fp16
__device__ __half g_c[(size_t)S_LEN * HID];     // ctx fp16 (written by flash)

__device__ __half g_qf[(size_t)NH * S_LEN * HD];
__device__ __half g_kf[(size_t)NH * S_LEN * HD];
__device__ __half g_vf[(size_t)NH * S_LEN * HD];

// ---------------- common PTX helpers ----------------
__device__ __forceinline__ void cp_async16(void* smem_dst, const void* gmem_src) {
    uint32_t s = (uint32_t)__cvta_generic_to_shared(smem_dst);
    asm volatile("cp.async.cg.shared.global [%0], [%1], 16;\n" :: "r"(s), "l"(gmem_src));
}
__device__ __forceinline__ void cp_commit() {
    asm volatile("cp.async.commit_group;\n");
}
template <int N>
__device__ __forceinline__ void cp_wait() {
    asm volatile("cp.async.wait_group %0;\n" :: "n"(N));
}

__device__ __forceinline__ void mma16816(float* c, const uint32_t* a, const uint32_t* b) {
    asm volatile(
        "mma.sync.aligned.m16n8k16.row.col.f32.f16.f16.f32 "
        "{%0,%1,%2,%3}, {%4,%5,%6,%7}, {%8,%9}, {%0,%1,%2,%3};\n"
        : "+f"(c[0]), "+f"(c[1]), "+f"(c[2]), "+f"(c[3])
        : "r"(a[0]), "r"(a[1]), "r"(a[2]), "r"(a[3]), "r"(b[0]), "r"(b[1]));
}

__device__ __forceinline__ void ldmx4(uint32_t* r, const void* p) {
    uint32_t a = (uint32_t)__cvta_generic_to_shared(p);
    asm volatile("ldmatrix.sync.aligned.m8n8.x4.shared.b16 {%0,%1,%2,%3}, [%4];"
                 : "=r"(r[0]), "=r"(r[1]), "=r"(r[2]), "=r"(r[3]) : "r"(a));
}
__device__ __forceinline__ void ldmx4t(uint32_t* r, const void* p) {
    uint32_t a = (uint32_t)__cvta_generic_to_shared(p);
    asm volatile("ldmatrix.sync.aligned.m8n8.x4.trans.shared.b16 {%0,%1,%2,%3}, [%4];"
                 : "=r"(r[0]), "=r"(r[1]), "=r"(r[2]), "=r"(r[3]) : "r"(a));
}

// ---------------- fp32 -> fp16 convert ----------------
__global__ __launch_bounds__(256) void to_fp16_kernel(
    const float* __restrict__ x, __half* __restrict__ y, int n4)
{
    int i = blockIdx.x * blockDim.x + threadIdx.x;
    if (i >= n4) return;
    float4 v = reinterpret_cast<const float4*>(x)[i];
    __half2* yp = reinterpret_cast<__half2*>(y);
    yp[2 * i]     = __floats2half2_rn(v.x, v.y);
    yp[2 * i + 1] = __floats2half2_rn(v.z, v.w);
}

// ---------------- HMMA GEMM (fp16, fp32 accum) ----------------
// 128x256 block tile, BK=32, 512 threads (16 warps 4x4), warp tile 32x64.
// 3-stage cp.async ring, one __syncthreads per stage.
#define GBK 32
#define SA     40                    // 32 + 8 pad (halfs)
#define SB     264                   // 256 + 8 pad
#define OA     0
#define OB     (128 * SA)            // 5120
#define BUFSZ  (OB + GBK * SB)       // 13568 halfs = 27136 B
#define GEMM_SMEM (3 * BUFSZ * 2)    // 81408 B

__global__ __launch_bounds__(512, 1) void mma_gemm_fp16(
    const __half* __restrict__ A, const __half* __restrict__ B,
    const float* __restrict__ bias, float* __restrict__ C,
    int M, int N, int K)
{
    extern __shared__ __align__(16) unsigned char smraw[];
    __half* sm = reinterpret_cast<__half*>(smraw);

    const int bx = blockIdx.x;     // N tile (256)
    const int by = blockIdx.y;     // M tile (128)
    const int tid = threadIdx.x;
    const int warp = tid >> 5;
    const int lane = tid & 31;
    const int warp_m = warp >> 2;      // 0..3  (32 rows)
    const int warp_n = warp & 3;       // 0..3  (64 cols)
    const int g  = lane >> 2;
    const int tg = lane & 3;

    const int nst = K / GBK;           // 64

    float acc[2][8][4];
    #pragma unroll
    for (int i = 0; i < 2; i++)
        #pragma unroll
        for (int j = 0; j < 8; j++)
            #pragma unroll
            for (int x = 0; x < 4; x++) acc[i][j][x] = 0.0f;

    auto issue = [&](int s) {
        const int k0 = s * GBK;
        __half* buf = sm + (s % 3) * BUFSZ;
        // A: 128 rows x 4 chunks = 512 chunks, 1/thread
        {
            int r = tid >> 2, c = tid & 3;
            size_t ga = (size_t)(by * 128 + r) * K + k0 + c * 8;
            cp_async16(buf + OA + r * SA + c * 8, A + ga);
        }
        // B: 32 rows x 32 chunks = 1024 chunks, 2/thread
        #pragma unroll
        for (int p = 0; p < 2; p++) {
            int q = tid + p * 512;
            int r = q >> 5, c = q & 31;
            size_t gb = (size_t)(k0 + r) * N + bx * 256 + c * 8;
            cp_async16(buf + OB + r * SB + c * 8, B + gb);
        }
    };

    issue(0); cp_commit();
    issue(1); cp_commit();

    const int a_row = lane & 15;
    const int a_colh = (lane >> 4) << 3;
    const int b_row = lane & 15;
    const int b_colh = (lane >> 4) << 3;

    for (int s = 0; s < nst; s++) {
        cp_wait<1>();
        __syncthreads();
        if (s + 2 < nst) { issue(s + 2); cp_commit(); }

        const __half* buf = sm + (s % 3) * BUFSZ;

        #pragma unroll
        for (int ks = 0; ks < GBK; ks += 16) {
            uint32_t ah[2][4];
            #pragma unroll
            for (int i = 0; i < 2; i++) {
                int ra = (warp_m * 32 + i * 16 + a_row) * SA + ks + a_colh;
                ldmx4(ah[i], buf + OA + ra);
            }
            #pragma unroll
            for (int jp = 0; jp < 4; jp++) {
                int rb = (ks + b_row) * SB + warp_n * 64 + jp * 16 + b_colh;
                uint32_t th[4];
                ldmx4t(th, buf + OB + rb);
                uint32_t b0[2] = {th[0], th[1]}, b1[2] = {th[2], th[3]};
                #pragma unroll
                for (int i = 0; i < 2; i++) {
                    mma16816(acc[i][2 * jp],     ah[i], b0);
                    mma16816(acc[i][2 * jp + 1], ah[i], b1);
                }
            }
        }
    }

    #pragma unroll
    for (int i = 0; i < 2; i++) {
        #pragma unroll
        for (int j = 0; j < 8; j++) {
            int row0 = by * 128 + warp_m * 32 + i * 16 + g;
            int col  = bx * 256 + warp_n * 64 + j * 8 + tg * 2;
            float b0 = bias[col], b1 = bias[col + 1];
            float2 v0 = make_float2(acc[i][j][0] + b0, acc[i][j][1] + b1);
            float2 v1 = make_float2(acc[i][j][2] + b0, acc[i][j][3] + b1);
            *reinterpret_cast<float2*>(C + (size_t)row0 * N + col) = v0;
            *reinterpret_cast<float2*>(C + (size_t)(row0 + 8) * N + col) = v1;
        }
    }
}

// ---------------- RoPE + scatter + fp16 convert ----------------
__global__ __launch_bounds__(128) void qkv_rope_kernel(
    const float* __restrict__ mixed,
    __half* __restrict__ Q, __half* __restrict__ K, __half* __restrict__ V)
{
    const int t = blockIdx.x;
    const int h = blockIdx.y;
    const int d = threadIdx.x;

    const float* base = mixed + (size_t)t * NQKV + h * (3 * HD);
    float q = base[d];
    float k = base[HD + d];
    float v = base[2 * HD + d];

    if (d < ROT) {
        const int i = d & 15;
        float inv_freq = 1.0f / powf(10000.0f, (float)(2 * i) * (1.0f / (float)ROT));
        float ang = (float)t * inv_freq;
        float s, c;
        sincosf(ang, &s, &c);
        if (d < 16) {
            q = q * c - base[d + 16] * s;
            k = k * c - base[HD + d + 16] * s;
        } else {
            q = q * c + base[d - 16] * s;
            k = k * c + base[HD + d - 16] * s;
        }
    }

    size_t off = ((size_t)h * S_LEN + t) * HD + d;
    Q[off] = __float2half_rn(q);
    K[off] = __float2half_rn(k);
    V[off] = __float2half_rn(v);
}

// ---------------- HMMA flash attention (fp16, causal) ----------------
// BM=128, BN=64, 256 threads (8 warps). K/V double-buffered via cp.async.
#define FBM 128
#define FBN 64
#define FSTR 136

#define FQ   0
#define FKV0 (128 * FSTR)            // 17408 halfs
#define KVARR (64 * FSTR)            // 8704 halfs per array
#define KVSTG (2 * KVARR)            // one stage: K, V
#define FLASH_SMEM ((FKV0 + 2 * KVSTG) * 2)   // 104448 B

__global__ __launch_bounds__(256, 1) void flash_mma_kernel(
    const __half* __restrict__ Q, const __half* __restrict__ K,
    const __half* __restrict__ V, __half* __restrict__ Cf)
{
    extern __shared__ __align__(16) unsigned char fsraw[];
    __half* fs = reinterpret_cast<__half*>(fsraw);

    const int h = blockIdx.y;
    const int m_tile = gridDim.x - 1 - blockIdx.x;
    const int m0 = m_tile * FBM;
    const int tid = threadIdx.x;
    const int warp = tid >> 5;
    const int lane = tid & 31;
    const int g  = lane >> 2;
    const int tg = lane & 3;

    const __half* qp = Q + ((size_t)h * S_LEN + m0) * HD;
    const __half* kp = K + (size_t)h * S_LEN * HD;
    const __half* vp = V + (size_t)h * S_LEN * HD;

    // load Q tile (sync, fp16)
    for (int idx = tid; idx < 2048; idx += 256) {
        int r = idx >> 4, c = (idx & 15) << 3;
        *reinterpret_cast<float4*>(fs + FQ + r * FSTR + c) =
            *reinterpret_cast<const float4*>(qp + (size_t)r * HD + c);
    }

    auto issue_kv = [&](int nt) {
        const int n0 = nt * FBN;
        __half* buf = fs + FKV0 + (nt & 1) * KVSTG;
        #pragma unroll
        for (int q = tid; q < 1024; q += 256) {
            int r = q >> 4, c = (q & 15) << 3;
            size_t go = (size_t)(n0 + r) * HD + c;
            int so = r * FSTR + c;
            cp_async16(buf + 0 * KVARR + so, kp + go);
            cp_async16(buf + 1 * KVARR + so, vp + go);
        }
    };

    float o[16][4];
    #pragma unroll
    for (int j = 0; j < 16; j++)
        #pragma unroll
        for (int x = 0; x < 4; x++) o[j][x] = 0.0f;
    float mrow0 = -1e30f, mrow1 = -1e30f, lrow0 = 0.0f, lrow1 = 0.0f;

    const float scale = 0.08838834764831845f;
    const int row0 = m0 + warp * 16 + g;
    const int row1 = row0 + 8;
    const int wrow_max = m0 + warp * 16 + 15;

    const int a_row = lane & 15;
    const int half8 = (lane >> 4) << 3;
    const int bk_colh = ((lane >> 3) & 1) << 3;

    const int ntiles = m0 / FBN + 2;
    issue_kv(0); cp_commit();

    for (int nt = 0; nt < ntiles; nt++) {
        const int n0 = nt * FBN;
        if (nt + 1 < ntiles) { issue_kv(nt + 1); cp_commit(); cp_wait<1>(); }
        else                 { cp_wait<0>(); }
        __syncthreads();

        if (n0 <= wrow_max) {
            const __half* kvb = fs + FKV0 + (nt & 1) * KVSTG;
            const __half* k_s = kvb;
            const __half* v_s = kvb + KVARR;

            float sacc[8][4];
            #pragma unroll
            for (int j = 0; j < 8; j++)
                #pragma unroll
                for (int x = 0; x < 4; x++) sacc[j][x] = 0.0f;

            #pragma unroll
            for (int ks = 0; ks < 8; ks++) {
                const int k = ks * 16;
                uint32_t aF[4];
                {
                    int ra = (warp * 16 + a_row) * FSTR + k + half8;
                    ldmx4(aF, fs + FQ + ra);
                }
                #pragma unroll
                for (int jp = 0; jp < 4; jp++) {
                    int rb = (jp * 16 + half8 + (lane & 7)) * FSTR + k + bk_colh;
                    uint32_t bF[4];
                    ldmx4(bF, k_s + rb);
                    uint32_t b0[2] = {bF[0], bF[1]}, b1[2] = {bF[2], bF[3]};
                    mma16816(sacc[2 * jp],     aF, b0);
                    mma16816(sacc[2 * jp + 1], aF, b1);
                }
            }

            const bool boundary = (n0 + FBN - 1 > m0);
            #pragma unroll
            for (int j = 0; j < 8; j++) {
                int c0 = n0 + j * 8 + 2 * tg;
                if (boundary) {
                    sacc[j][0] = (c0     > row0) ? -1e30f : sacc[j][0] * scale;
                    sacc[j][1] = (c0 + 1 > row0) ? -1e30f : sacc[j][1] * scale;
                    sacc[j][2] = (c0     > row1) ? -1e30f : sacc[j][2] * scale;
                    sacc[j][3] = (c0 + 1 > row1) ? -1e30f : sacc[j][3] * scale;
                } else {
                    sacc[j][0] *= scale; sacc[j][1] *= scale;
                    sacc[j][2] *= scale; sacc[j][3] *= scale;
                }
            }

            float mx0 = -1e30f, mx1 = -1e30f;
            #pragma unroll
            for (int j = 0; j < 8; j++) {
                mx0 = fmaxf(mx0, fmaxf(sacc[j][0], sacc[j][1]));
                mx1 = fmaxf(mx1, fmaxf(sacc[j][2], sacc[j][3]));
            }
            mx0 = fmaxf(mx0, __shfl_xor_sync(0xffffffffu, mx0, 1));
            mx0 = fmaxf(mx0, __shfl_xor_sync(0xffffffffu, mx0, 2));
            mx1 = fmaxf(mx1, __shfl_xor_sync(0xffffffffu, mx1, 1));
            mx1 = fmaxf(mx1, __shfl_xor_sync(0xffffffffu, mx1, 2));

            float mn0 = fmaxf(mrow0, mx0);
            float mn1 = fmaxf(mrow1, mx1);
            float alpha0 = __expf(mrow0 - mn0);
            float alpha1 = __expf(mrow1 - mn1);
            mrow0 = mn0; mrow1 = mn1;

            float sum0 = 0.0f, sum1 = 0.0f;
            #pragma unroll
            for (int j = 0; j < 8; j++) {
                sacc[j][0] = __expf(sacc[j][0] - mn0);
                sacc[j][1] = __expf(sacc[j][1] - mn0);
                sacc[j][2] = __expf(sacc[j][2] - mn1);
                sacc[j][3] = __expf(sacc[j][3] - mn1);
                sum0 += sacc[j][0] + sacc[j][1];
                sum1 += sacc[j][2] + sacc[j][3];
            }
            sum0 += __shfl_xor_sync(0xffffffffu, sum0, 1);
            sum0 += __shfl_xor_sync(0xffffffffu, sum0, 2);
            sum1 += __shfl_xor_sync(0xffffffffu, sum1, 1);
            sum1 += __shfl_xor_sync(0xffffffffu, sum1, 2);
            lrow0 = lrow0 * alpha0 + sum0;
            lrow1 = lrow1 * alpha1 + sum1;

            #pragma unroll
            for (int j = 0; j < 16; j++) {
                o[j][0] *= alpha0; o[j][1] *= alpha0;
                o[j][2] *= alpha1; o[j][3] *= alpha1;
            }

            // O += P V, P a-frags packed straight from registers (fp16)
            #pragma unroll
            for (int kk = 0; kk < 4; kk++) {
                uint32_t pa[4];
                #pragma unroll
                for (int half = 0; half < 2; half++) {
                    const float* sv = sacc[2 * kk + half];
                    __half2 h0 = __floats2half2_rn(sv[0], sv[1]);
                    __half2 h1 = __floats2half2_rn(sv[2], sv[3]);
                    pa[2 * half]     = *reinterpret_cast<uint32_t*>(&h0);
                    pa[2 * half + 1] = *reinterpret_cast<uint32_t*>(&h1);
                }
                #pragma unroll
                for (int jp = 0; jp < 8; jp++) {
                    int rv = (kk * 16 + a_row) * FSTR + jp * 16 + half8;
                    uint32_t vF[4];
                    ldmx4t(vF, v_s + rv);
                    uint32_t v0[2] = {vF[0], vF[1]}, v1[2] = {vF[2], vF[3]};
                    mma16816(o[2 * jp],     pa, v0);
                    mma16816(o[2 * jp + 1], pa, v1);
                }
            }
        }
        __syncthreads();
    }

    // epilogue: O /= l, write fp16 ctx
    float inv0 = 1.0f / lrow0;
    float inv1 = 1.0f / lrow1;
    #pragma unroll
    for (int jt = 0; jt < 16; jt++) {
        int col = h * HD + jt * 8 + 2 * tg;
        __half2 r0 = __floats2half2_rn(o[jt][0] * inv0, o[jt][1] * inv0);
        __half2 r1 = __floats2half2_rn(o[jt][2] * inv1, o[jt][3] * inv1);
        *reinterpret_cast<__half2*>(Cf + (size_t)row0 * HID + col) = r0;
        *reinterpret_cast<__half2*>(Cf + (size_t)row1 * HID + col) = r1;
    }
}

// ---------------- launch ----------------
extern "C" void kernel_launch(void* const* d_in, const int* in_sizes, int n_in,
                              void* d_out, int out_size)
{
    const float* hidden  = (const float*)d_in[0];
    const float* W_qkv   = (const float*)d_in[1];
    const float* b_qkv   = (const float*)d_in[2];
    const float* W_dense = (const float*)d_in[3];
    const float* b_dense = (const float*)d_in[4];
    float* out = (float*)d_out;

    float* mixed;
    __half *a, *b, *w, *c, *qf, *kf, *vf;
    cudaGetSymbolAddress((void**)&mixed, g_mixed);
    cudaGetSymbolAddress((void**)&a,  g_a);
    cudaGetSymbolAddress((void**)&b,  g_b);
    cudaGetSymbolAddress((void**)&w,  g_w);
    cudaGetSymbolAddress((void**)&c,  g_c);
    cudaGetSymbolAddress((void**)&qf, g_qf);
    cudaGetSymbolAddress((void**)&kf, g_kf);
    cudaGetSymbolAddress((void**)&vf, g_vf);

    cudaFuncSetAttribute(mma_gemm_fp16,
                         cudaFuncAttributeMaxDynamicSharedMemorySize, GEMM_SMEM);
    cudaFuncSetAttribute(flash_mma_kernel,
                         cudaFuncAttributeMaxDynamicSharedMemorySize, FLASH_SMEM);

    // 0) fp16 conversions
    {
        int n4 = S_LEN * HID / 4;
        to_fp16_kernel<<<(n4 + 255) / 256, 256>>>(hidden, a, n4);
        int w4 = HID * NQKV / 4;
        to_fp16_kernel<<<(w4 + 255) / 256, 256>>>(W_qkv, b, w4);
        int d4 = HID * HID / 4;
        to_fp16_kernel<<<(d4 + 255) / 256, 256>>>(W_dense, w, d4);
    }

    // 1) QKV projection (+bias)
    {
        dim3 grid(NQKV / 256, S_LEN / 128);
        mma_gemm_fp16<<<grid, 512, GEMM_SMEM>>>(a, b, b_qkv, mixed,
                                                S_LEN, NQKV, HID);
    }

    // 2) RoPE + scatter + fp16
    qkv_rope_kernel<<<dim3(S_LEN, NH), 128>>>(mixed, qf, kf, vf);

    // 3) causal flash attention (fp16); writes ctx fp16
    flash_mma_kernel<<<dim3(S_LEN / FBM, NH), 256, FLASH_SMEM>>>(qf, kf, vf, c);

    // 4) dense projection (+bias)
    {
        dim3 grid(HID / 256, S_LEN / 128);
        mma_gemm_fp16<<<grid, 512, GEMM_SMEM>>>(c, w, b_dense, out,
                                                S_LEN, HID, HID);
    }
}

// round 12
// speedup vs baseline: 2.2275x; 1.0721x over previous
#include <cuda_runtime.h>
#include <cuda_fp16.h>
#include <cstdint>
#include <math.h>

using std::uint32_t;

// ---------------- problem constants ----------------
#define S_LEN 2048
#define HID   2048
#define NH    16
#define HD    128
#define NQKV  6144   // 3 * HID
#define ROT   32

// ---------------- scratch (device globals; no runtime alloc) ----------------
__device__ __half g_mixed[(size_t)S_LEN * NQKV];   // fp16 QKV output

__device__ __half g_a[(size_t)S_LEN * HID];     // hidden fp16
__device__ __half g_b[(size_t)HID * NQKV];      // W_qkv fp16
__device__ __half g_w[(size_t)HID * HID];       // W_dense fp16
__device__ __half g_c[(size_t)S_LEN * HID];     // ctx fp16 (written by flash)

__device__ __half g_qf[(size_t)NH * S_LEN * HD];
__device__ __half g_kf[(size_t)NH * S_LEN * HD];
__device__ __half g_vf[(size_t)NH * S_LEN * HD];

// ---------------- common PTX helpers ----------------
__device__ __forceinline__ void cp_async16(void* smem_dst, const void* gmem_src) {
    uint32_t s = (uint32_t)__cvta_generic_to_shared(smem_dst);
    asm volatile("cp.async.cg.shared.global [%0], [%1], 16;\n" :: "r"(s), "l"(gmem_src));
}
__device__ __forceinline__ void cp_commit() {
    asm volatile("cp.async.commit_group;\n");
}
template <int N>
__device__ __forceinline__ void cp_wait() {
    asm volatile("cp.async.wait_group %0;\n" :: "n"(N));
}

__device__ __forceinline__ void mma16816(float* c, const uint32_t* a, const uint32_t* b) {
    asm volatile(
        "mma.sync.aligned.m16n8k16.row.col.f32.f16.f16.f32 "
        "{%0,%1,%2,%3}, {%4,%5,%6,%7}, {%8,%9}, {%0,%1,%2,%3};\n"
        : "+f"(c[0]), "+f"(c[1]), "+f"(c[2]), "+f"(c[3])
        : "r"(a[0]), "r"(a[1]), "r"(a[2]), "r"(a[3]), "r"(b[0]), "r"(b[1]));
}

__device__ __forceinline__ void ldmx4(uint32_t* r, const void* p) {
    uint32_t a = (uint32_t)__cvta_generic_to_shared(p);
    asm volatile("ldmatrix.sync.aligned.m8n8.x4.shared.b16 {%0,%1,%2,%3}, [%4];"
                 : "=r"(r[0]), "=r"(r[1]), "=r"(r[2]), "=r"(r[3]) : "r"(a));
}
__device__ __forceinline__ void ldmx4t(uint32_t* r, const void* p) {
    uint32_t a = (uint32_t)__cvta_generic_to_shared(p);
    asm volatile("ldmatrix.sync.aligned.m8n8.x4.trans.shared.b16 {%0,%1,%2,%3}, [%4];"
                 : "=r"(r[0]), "=r"(r[1]), "=r"(r[2]), "=r"(r[3]) : "r"(a));
}

// ---------------- fp32 -> fp16 convert ----------------
__global__ __launch_bounds__(256) void to_fp16_kernel(
    const float* __restrict__ x, __half* __restrict__ y, int n4)
{
    int i = blockIdx.x * blockDim.x + threadIdx.x;
    if (i >= n4) return;
    float4 v = reinterpret_cast<const float4*>(x)[i];
    __half2* yp = reinterpret_cast<__half2*>(y);
    yp[2 * i]     = __floats2half2_rn(v.x, v.y);
    yp[2 * i + 1] = __floats2half2_rn(v.z, v.w);
}

// ---------------- HMMA GEMM (fp16, fp32 accum) ----------------
// 128x256 block tile, BK=64, 512 threads (16 warps 4x4), warp tile 32x64.
// 3-stage cp.async ring, one __syncthreads per stage.
// Templated output: fp16 (OutHalf=true) or fp32.
#define GBK 64
#define SA     72                    // 64 + 8 pad (halfs)
#define SB     264                   // 256 + 8 pad
#define OA     0
#define OB     (128 * SA)            // 9216
#define BUFSZ  (OB + GBK * SB)       // 26112 halfs = 52224 B
#define GEMM_SMEM (3 * BUFSZ * 2)    // 156672 B

template <bool OutHalf>
__global__ __launch_bounds__(512, 1) void mma_gemm_fp16(
    const __half* __restrict__ A, const __half* __restrict__ B,
    const float* __restrict__ bias, void* __restrict__ Cv,
    int M, int N, int K)
{
    extern __shared__ __align__(16) unsigned char smraw[];
    __half* sm = reinterpret_cast<__half*>(smraw);

    const int bx = blockIdx.x;     // N tile (256)
    const int by = blockIdx.y;     // M tile (128)
    const int tid = threadIdx.x;
    const int warp = tid >> 5;
    const int lane = tid & 31;
    const int warp_m = warp >> 2;      // 0..3  (32 rows)
    const int warp_n = warp & 3;       // 0..3  (64 cols)
    const int g  = lane >> 2;
    const int tg = lane & 3;

    const int nst = K / GBK;           // 32

    float acc[2][8][4];
    #pragma unroll
    for (int i = 0; i < 2; i++)
        #pragma unroll
        for (int j = 0; j < 8; j++)
            #pragma unroll
            for (int x = 0; x < 4; x++) acc[i][j][x] = 0.0f;

    auto issue = [&](int s) {
        const int k0 = s * GBK;
        __half* buf = sm + (s % 3) * BUFSZ;
        // A: 128 rows x 8 chunks = 1024 chunks, 2/thread
        #pragma unroll
        for (int p = 0; p < 2; p++) {
            int q = tid + p * 512;
            int r = q >> 3, c = q & 7;
            size_t ga = (size_t)(by * 128 + r) * K + k0 + c * 8;
            cp_async16(buf + OA + r * SA + c * 8, A + ga);
        }
        // B: 64 rows x 32 chunks = 2048 chunks, 4/thread
        #pragma unroll
        for (int p = 0; p < 4; p++) {
            int q = tid + p * 512;
            int r = q >> 5, c = q & 31;
            size_t gb = (size_t)(k0 + r) * N + bx * 256 + c * 8;
            cp_async16(buf + OB + r * SB + c * 8, B + gb);
        }
    };

    issue(0); cp_commit();
    issue(1); cp_commit();

    const int a_row = lane & 15;
    const int a_colh = (lane >> 4) << 3;
    const int b_row = lane & 15;
    const int b_colh = (lane >> 4) << 3;

    for (int s = 0; s < nst; s++) {
        cp_wait<1>();
        __syncthreads();
        if (s + 2 < nst) { issue(s + 2); cp_commit(); }

        const __half* buf = sm + (s % 3) * BUFSZ;

        #pragma unroll
        for (int ks = 0; ks < GBK; ks += 16) {
            uint32_t ah[2][4];
            #pragma unroll
            for (int i = 0; i < 2; i++) {
                int ra = (warp_m * 32 + i * 16 + a_row) * SA + ks + a_colh;
                ldmx4(ah[i], buf + OA + ra);
            }
            #pragma unroll
            for (int jp = 0; jp < 4; jp++) {
                int rb = (ks + b_row) * SB + warp_n * 64 + jp * 16 + b_colh;
                uint32_t th[4];
                ldmx4t(th, buf + OB + rb);
                uint32_t b0[2] = {th[0], th[1]}, b1[2] = {th[2], th[3]};
                #pragma unroll
                for (int i = 0; i < 2; i++) {
                    mma16816(acc[i][2 * jp],     ah[i], b0);
                    mma16816(acc[i][2 * jp + 1], ah[i], b1);
                }
            }
        }
    }

    #pragma unroll
    for (int i = 0; i < 2; i++) {
        #pragma unroll
        for (int j = 0; j < 8; j++) {
            int row0 = by * 128 + warp_m * 32 + i * 16 + g;
            int col  = bx * 256 + warp_n * 64 + j * 8 + tg * 2;
            float b0 = bias[col], b1 = bias[col + 1];
            float c00 = acc[i][j][0] + b0, c01 = acc[i][j][1] + b1;
            float c10 = acc[i][j][2] + b0, c11 = acc[i][j][3] + b1;
            if (OutHalf) {
                __half* C = reinterpret_cast<__half*>(Cv);
                *reinterpret_cast<__half2*>(C + (size_t)row0 * N + col) =
                    __floats2half2_rn(c00, c01);
                *reinterpret_cast<__half2*>(C + (size_t)(row0 + 8) * N + col) =
                    __floats2half2_rn(c10, c11);
            } else {
                float* C = reinterpret_cast<float*>(Cv);
                *reinterpret_cast<float2*>(C + (size_t)row0 * N + col) =
                    make_float2(c00, c01);
                *reinterpret_cast<float2*>(C + (size_t)(row0 + 8) * N + col) =
                    make_float2(c10, c11);
            }
        }
    }
}

// ---------------- RoPE + scatter (fp16 in/out) ----------------
__global__ __launch_bounds__(128) void qkv_rope_kernel(
    const __half* __restrict__ mixed,
    __half* __restrict__ Q, __half* __restrict__ K, __half* __restrict__ V)
{
    const int t = blockIdx.x;
    const int h = blockIdx.y;
    const int d = threadIdx.x;

    const __half* base = mixed + (size_t)t * NQKV + h * (3 * HD);
    float q = __half2float(base[d]);
    float k = __half2float(base[HD + d]);
    float v = __half2float(base[2 * HD + d]);

    if (d < ROT) {
        const int i = d & 15;
        float inv_freq = 1.0f / powf(10000.0f, (float)(2 * i) * (1.0f / (float)ROT));
        float ang = (float)t * inv_freq;
        float s, c;
        sincosf(ang, &s, &c);
        if (d < 16) {
            q = q * c - __half2float(base[d + 16]) * s;
            k = k * c - __half2float(base[HD + d + 16]) * s;
        } else {
            q = q * c + __half2float(base[d - 16]) * s;
            k = k * c + __half2float(base[HD + d - 16]) * s;
        }
    }

    size_t off = ((size_t)h * S_LEN + t) * HD + d;
    Q[off] = __float2half_rn(q);
    K[off] = __float2half_rn(k);
    V[off] = __float2half_rn(v);
}

// ---------------- HMMA flash attention (fp16, causal) ----------------
#define FBM 128
#define FBN 64
#define FSTR 136

#define FQ   0
#define FKV0 (128 * FSTR)            // 17408 halfs
#define KVARR (64 * FSTR)            // 8704 halfs per array
#define KVSTG (2 * KVARR)            // one stage: K, V
#define FLASH_SMEM ((FKV0 + 2 * KVSTG) * 2)   // 104448 B

__global__ __launch_bounds__(256, 1) void flash_mma_kernel(
    const __half* __restrict__ Q, const __half* __restrict__ K,
    const __half* __restrict__ V, __half* __restrict__ Cf)
{
    extern __shared__ __align__(16) unsigned char fsraw[];
    __half* fs = reinterpret_cast<__half*>(fsraw);

    const int h = blockIdx.y;
    const int m_tile = gridDim.x - 1 - blockIdx.x;
    const int m0 = m_tile * FBM;
    const int tid = threadIdx.x;
    const int warp = tid >> 5;
    const int lane = tid & 31;
    const int g  = lane >> 2;
    const int tg = lane & 3;

    const __half* qp = Q + ((size_t)h * S_LEN + m0) * HD;
    const __half* kp = K + (size_t)h * S_LEN * HD;
    const __half* vp = V + (size_t)h * S_LEN * HD;

    for (int idx = tid; idx < 2048; idx += 256) {
        int r = idx >> 4, c = (idx & 15) << 3;
        *reinterpret_cast<float4*>(fs + FQ + r * FSTR + c) =
            *reinterpret_cast<const float4*>(qp + (size_t)r * HD + c);
    }

    auto issue_kv = [&](int nt) {
        const int n0 = nt * FBN;
        __half* buf = fs + FKV0 + (nt & 1) * KVSTG;
        #pragma unroll
        for (int q = tid; q < 1024; q += 256) {
            int r = q >> 4, c = (q & 15) << 3;
            size_t go = (size_t)(n0 + r) * HD + c;
            int so = r * FSTR + c;
            cp_async16(buf + 0 * KVARR + so, kp + go);
            cp_async16(buf + 1 * KVARR + so, vp + go);
        }
    };

    float o[16][4];
    #pragma unroll
    for (int j = 0; j < 16; j++)
        #pragma unroll
        for (int x = 0; x < 4; x++) o[j][x] = 0.0f;
    float mrow0 = -1e30f, mrow1 = -1e30f, lrow0 = 0.0f, lrow1 = 0.0f;

    const float scale = 0.08838834764831845f;
    const int row0 = m0 + warp * 16 + g;
    const int row1 = row0 + 8;
    const int wrow_max = m0 + warp * 16 + 15;

    const int a_row = lane & 15;
    const int half8 = (lane >> 4) << 3;
    const int bk_colh = ((lane >> 3) & 1) << 3;

    const int ntiles = m0 / FBN + 2;
    issue_kv(0); cp_commit();

    for (int nt = 0; nt < ntiles; nt++) {
        const int n0 = nt * FBN;
        if (nt + 1 < ntiles) { issue_kv(nt + 1); cp_commit(); cp_wait<1>(); }
        else                 { cp_wait<0>(); }
        __syncthreads();

        if (n0 <= wrow_max) {
            const __half* kvb = fs + FKV0 + (nt & 1) * KVSTG;
            const __half* k_s = kvb;
            const __half* v_s = kvb + KVARR;

            float sacc[8][4];
            #pragma unroll
            for (int j = 0; j < 8; j++)
                #pragma unroll
                for (int x = 0; x < 4; x++) sacc[j][x] = 0.0f;

            #pragma unroll
            for (int ks = 0; ks < 8; ks++) {
                const int k = ks * 16;
                uint32_t aF[4];
                {
                    int ra = (warp * 16 + a_row) * FSTR + k + half8;
                    ldmx4(aF, fs + FQ + ra);
                }
                #pragma unroll
                for (int jp = 0; jp < 4; jp++) {
                    int rb = (jp * 16 + half8 + (lane & 7)) * FSTR + k + bk_colh;
                    uint32_t bF[4];
                    ldmx4(bF, k_s + rb);
                    uint32_t b0[2] = {bF[0], bF[1]}, b1[2] = {bF[2], bF[3]};
                    mma16816(sacc[2 * jp],     aF, b0);
                    mma16816(sacc[2 * jp + 1], aF, b1);
                }
            }

            const bool boundary = (n0 + FBN - 1 > m0);
            #pragma unroll
            for (int j = 0; j < 8; j++) {
                int c0 = n0 + j * 8 + 2 * tg;
                if (boundary) {
                    sacc[j][0] = (c0     > row0) ? -1e30f : sacc[j][0] * scale;
                    sacc[j][1] = (c0 + 1 > row0) ? -1e30f : sacc[j][1] * scale;
                    sacc[j][2] = (c0     > row1) ? -1e30f : sacc[j][2] * scale;
                    sacc[j][3] = (c0 + 1 > row1) ? -1e30f : sacc[j][3] * scale;
                } else {
                    sacc[j][0] *= scale; sacc[j][1] *= scale;
                    sacc[j][2] *= scale; sacc[j][3] *= scale;
                }
            }

            float mx0 = -1e30f, mx1 = -1e30f;
            #pragma unroll
            for (int j = 0; j < 8; j++) {
                mx0 = fmaxf(mx0, fmaxf(sacc[j][0], sacc[j][1]));
                mx1 = fmaxf(mx1, fmaxf(sacc[j][2], sacc[j][3]));
            }
            mx0 = fmaxf(mx0, __shfl_xor_sync(0xffffffffu, mx0, 1));
            mx0 = fmaxf(mx0, __shfl_xor_sync(0xffffffffu, mx0, 2));
            mx1 = fmaxf(mx1, __shfl_xor_sync(0xffffffffu, mx1, 1));
            mx1 = fmaxf(mx1, __shfl_xor_sync(0xffffffffu, mx1, 2));

            float mn0 = fmaxf(mrow0, mx0);
            float mn1 = fmaxf(mrow1, mx1);
            float alpha0 = __expf(mrow0 - mn0);
            float alpha1 = __expf(mrow1 - mn1);
            mrow0 = mn0; mrow1 = mn1;

            float sum0 = 0.0f, sum1 = 0.0f;
            #pragma unroll
            for (int j = 0; j < 8; j++) {
                sacc[j][0] = __expf(sacc[j][0] - mn0);
                sacc[j][1] = __expf(sacc[j][1] - mn0);
                sacc[j][2] = __expf(sacc[j][2] - mn1);
                sacc[j][3] = __expf(sacc[j][3] - mn1);
                sum0 += sacc[j][0] + sacc[j][1];
                sum1 += sacc[j][2] + sacc[j][3];
            }
            sum0 += __shfl_xor_sync(0xffffffffu, sum0, 1);
            sum0 += __shfl_xor_sync(0xffffffffu, sum0, 2);
            sum1 += __shfl_xor_sync(0xffffffffu, sum1, 1);
            sum1 += __shfl_xor_sync(0xffffffffu, sum1, 2);
            lrow0 = lrow0 * alpha0 + sum0;
            lrow1 = lrow1 * alpha1 + sum1;

            #pragma unroll
            for (int j = 0; j < 16; j++) {
                o[j][0] *= alpha0; o[j][1] *= alpha0;
                o[j][2] *= alpha1; o[j][3] *= alpha1;
            }

            #pragma unroll
            for (int kk = 0; kk < 4; kk++) {
                uint32_t pa[4];
                #pragma unroll
                for (int half = 0; half < 2; half++) {
                    const float* sv = sacc[2 * kk + half];
                    __half2 h0 = __floats2half2_rn(sv[0], sv[1]);
                    __half2 h1 = __floats2half2_rn(sv[2], sv[3]);
                    pa[2 * half]     = *reinterpret_cast<uint32_t*>(&h0);
                    pa[2 * half + 1] = *reinterpret_cast<uint32_t*>(&h1);
                }
                #pragma unroll
                for (int jp = 0; jp < 8; jp++) {
                    int rv = (kk * 16 + a_row) * FSTR + jp * 16 + half8;
                    uint32_t vF[4];
                    ldmx4t(vF, v_s + rv);
                    uint32_t v0[2] = {vF[0], vF[1]}, v1[2] = {vF[2], vF[3]};
                    mma16816(o[2 * jp],     pa, v0);
                    mma16816(o[2 * jp + 1], pa, v1);
                }
            }
        }
        __syncthreads();
    }

    float inv0 = 1.0f / lrow0;
    float inv1 = 1.0f / lrow1;
    #pragma unroll
    for (int jt = 0; jt < 16; jt++) {
        int col = h * HD + jt * 8 + 2 * tg;
        __half2 r0 = __floats2half2_rn(o[jt][0] * inv0, o[jt][1] * inv0);
        __half2 r1 = __floats2half2_rn(o[jt][2] * inv1, o[jt][3] * inv1);
        *reinterpret_cast<__half2*>(Cf + (size_t)row0 * HID + col) = r0;
        *reinterpret_cast<__half2*>(Cf + (size_t)row1 * HID + col) = r1;
    }
}

// ---------------- launch ----------------
extern "C" void kernel_launch(void* const* d_in, const int* in_sizes, int n_in,
                              void* d_out, int out_size)
{
    const float* hidden  = (const float*)d_in[0];
    const float* W_qkv   = (const float*)d_in[1];
    const float* b_qkv   = (const float*)d_in[2];
    const float* W_dense = (const float*)d_in[3];
    const float* b_dense = (const float*)d_in[4];
    float* out = (float*)d_out;

    __half *mixed, *a, *b, *w, *c, *qf, *kf, *vf;
    cudaGetSymbolAddress((void**)&mixed, g_mixed);
    cudaGetSymbolAddress((void**)&a,  g_a);
    cudaGetSymbolAddress((void**)&b,  g_b);
    cudaGetSymbolAddress((void**)&w,  g_w);
    cudaGetSymbolAddress((void**)&c,  g_c);
    cudaGetSymbolAddress((void**)&qf, g_qf);
    cudaGetSymbolAddress((void**)&kf, g_kf);
    cudaGetSymbolAddress((void**)&vf, g_vf);

    cudaFuncSetAttribute(mma_gemm_fp16<true>,
                         cudaFuncAttributeMaxDynamicSharedMemorySize, GEMM_SMEM);
    cudaFuncSetAttribute(mma_gemm_fp16<false>,
                         cudaFuncAttributeMaxDynamicSharedMemorySize, GEMM_SMEM);
    cudaFuncSetAttribute(flash_mma_kernel,
                         cudaFuncAttributeMaxDynamicSharedMemorySize, FLASH_SMEM);

    // 0) fp16 conversions
    {
        int n4 = S_LEN * HID / 4;
        to_fp16_kernel<<<(n4 + 255) / 256, 256>>>(hidden, a, n4);
        int w4 = HID * NQKV / 4;
        to_fp16_kernel<<<(w4 + 255) / 256, 256>>>(W_qkv, b, w4);
        int d4 = HID * HID / 4;
        to_fp16_kernel<<<(d4 + 255) / 256, 256>>>(W_dense, w, d4);
    }

    // 1) QKV projection (+bias) -> fp16 mixed
    {
        dim3 grid(NQKV / 256, S_LEN / 128);
        mma_gemm_fp16<true><<<grid, 512, GEMM_SMEM>>>(a, b, b_qkv, mixed,
                                                      S_LEN, NQKV, HID);
    }

    // 2) RoPE + scatter (fp16)
    qkv_rope_kernel<<<dim3(S_LEN, NH), 128>>>(mixed, qf, kf, vf);

    // 3) causal flash attention (fp16); writes ctx fp16
    flash_mma_kernel<<<dim3(S_LEN / FBM, NH), 256, FLASH_SMEM>>>(qf, kf, vf, c);

    // 4) dense projection (+bias) -> fp32 out
    {
        dim3 grid(HID / 256, S_LEN / 128);
        mma_gemm_fp16<false><<<grid, 512, GEMM_SMEM>>>(c, w, b_dense, out,
                                                       S_LEN, HID, HID);
    }
}

// round 13
// speedup vs baseline: 2.3068x; 1.0356x over previous
#include <cuda_runtime.h>
#include <cuda_fp16.h>
#include <cstdint>
#include <math.h>

using std::uint32_t;

// ---------------- problem constants ----------------
#define S_LEN 2048
#define HID   2048
#define NH    16
#define HD    128
#define NQKV  6144   // 3 * HID
#define ROT   32

// ---------------- scratch (device globals; no runtime alloc) ----------------
__device__ __half g_mixed[(size_t)S_LEN * NQKV];   // fp16 QKV output

__device__ __half g_a[(size_t)S_LEN * HID];     // hidden fp16
__device__ __half g_b[(size_t)HID * NQKV];      // W_qkv fp16
__device__ __half g_w[(size_t)HID * HID];       // W_dense fp16
__device__ __half g_c[(size_t)S_LEN * HID];     // ctx fp16 (written by flash)

__device__ __half g_qf[(size_t)NH * S_LEN * HD];
__device__ __half g_kf[(size_t)NH * S_LEN * HD];
__device__ __half g_vf[(size_t)NH * S_LEN * HD];

// ---------------- common PTX helpers ----------------
__device__ __forceinline__ void cp_async16(void* smem_dst, const void* gmem_src) {
    uint32_t s = (uint32_t)__cvta_generic_to_shared(smem_dst);
    asm volatile("cp.async.cg.shared.global [%0], [%1], 16;\n" :: "r"(s), "l"(gmem_src));
}
__device__ __forceinline__ void cp_commit() {
    asm volatile("cp.async.commit_group;\n");
}
template <int N>
__device__ __forceinline__ void cp_wait() {
    asm volatile("cp.async.wait_group %0;\n" :: "n"(N));
}

__device__ __forceinline__ void mma16816(float* c, const uint32_t* a, const uint32_t* b) {
    asm volatile(
        "mma.sync.aligned.m16n8k16.row.col.f32.f16.f16.f32 "
        "{%0,%1,%2,%3}, {%4,%5,%6,%7}, {%8,%9}, {%0,%1,%2,%3};\n"
        : "+f"(c[0]), "+f"(c[1]), "+f"(c[2]), "+f"(c[3])
        : "r"(a[0]), "r"(a[1]), "r"(a[2]), "r"(a[3]), "r"(b[0]), "r"(b[1]));
}

__device__ __forceinline__ void ldmx4(uint32_t* r, const void* p) {
    uint32_t a = (uint32_t)__cvta_generic_to_shared(p);
    asm volatile("ldmatrix.sync.aligned.m8n8.x4.shared.b16 {%0,%1,%2,%3}, [%4];"
                 : "=r"(r[0]), "=r"(r[1]), "=r"(r[2]), "=r"(r[3]) : "r"(a));
}
__device__ __forceinline__ void ldmx4t(uint32_t* r, const void* p) {
    uint32_t a = (uint32_t)__cvta_generic_to_shared(p);
    asm volatile("ldmatrix.sync.aligned.m8n8.x4.trans.shared.b16 {%0,%1,%2,%3}, [%4];"
                 : "=r"(r[0]), "=r"(r[1]), "=r"(r[2]), "=r"(r[3]) : "r"(a));
}

// ---------------- fp32 -> fp16 convert ----------------
__global__ __launch_bounds__(256) void to_fp16_kernel(
    const float* __restrict__ x, __half* __restrict__ y, int n4)
{
    int i = blockIdx.x * blockDim.x + threadIdx.x;
    if (i >= n4) return;
    float4 v = reinterpret_cast<const float4*>(x)[i];
    __half2* yp = reinterpret_cast<__half2*>(y);
    yp[2 * i]     = __floats2half2_rn(v.x, v.y);
    yp[2 * i + 1] = __floats2half2_rn(v.z, v.w);
}

// ---------------- HMMA GEMM (fp16, fp32 accum) ----------------
// 128x128 block tile, BK=64, 256 threads (8 warps 4x2), warp tile 32x64.
// 3-stage cp.async ring; 105 KB smem/CTA -> 2 CTAs/SM for barrier overlap.
#define GBK 64
#define SA     72                    // 64 + 8 pad (halfs)
#define SB     136                   // 128 + 8 pad
#define OA     0
#define OB     (128 * SA)            // 9216
#define BUFSZ  (OB + GBK * SB)       // 17920 halfs = 35840 B
#define GEMM_SMEM (3 * BUFSZ * 2)    // 107520 B

template <bool OutHalf>
__global__ __launch_bounds__(256, 2) void mma_gemm_fp16(
    const __half* __restrict__ A, const __half* __restrict__ B,
    const float* __restrict__ bias, void* __restrict__ Cv,
    int M, int N, int K)
{
    extern __shared__ __align__(16) unsigned char smraw[];
    __half* sm = reinterpret_cast<__half*>(smraw);

    const int bx = blockIdx.x;     // N tile (128)
    const int by = blockIdx.y;     // M tile (128)
    const int tid = threadIdx.x;
    const int warp = tid >> 5;
    const int lane = tid & 31;
    const int warp_m = warp & 3;       // 0..3  (32 rows)
    const int warp_n = warp >> 2;      // 0..1  (64 cols)
    const int g  = lane >> 2;
    const int tg = lane & 3;

    const int nst = K / GBK;           // 32

    float acc[2][8][4];
    #pragma unroll
    for (int i = 0; i < 2; i++)
        #pragma unroll
        for (int j = 0; j < 8; j++)
            #pragma unroll
            for (int x = 0; x < 4; x++) acc[i][j][x] = 0.0f;

    auto issue = [&](int s) {
        const int k0 = s * GBK;
        __half* buf = sm + (s % 3) * BUFSZ;
        // A: 128 rows x 8 chunks = 1024 chunks, 4/thread
        #pragma unroll
        for (int p = 0; p < 4; p++) {
            int q = tid + p * 256;
            int r = q >> 3, c = q & 7;
            size_t ga = (size_t)(by * 128 + r) * K + k0 + c * 8;
            cp_async16(buf + OA + r * SA + c * 8, A + ga);
        }
        // B: 64 rows x 16 chunks = 1024 chunks, 4/thread
        #pragma unroll
        for (int p = 0; p < 4; p++) {
            int q = tid + p * 256;
            int r = q >> 4, c = q & 15;
            size_t gb = (size_t)(k0 + r) * N + bx * 128 + c * 8;
            cp_async16(buf + OB + r * SB + c * 8, B + gb);
        }
    };

    issue(0); cp_commit();
    issue(1); cp_commit();

    const int a_row = lane & 15;
    const int a_colh = (lane >> 4) << 3;
    const int b_row = lane & 15;
    const int b_colh = (lane >> 4) << 3;

    for (int s = 0; s < nst; s++) {
        cp_wait<1>();
        __syncthreads();
        if (s + 2 < nst) { issue(s + 2); cp_commit(); }

        const __half* buf = sm + (s % 3) * BUFSZ;

        #pragma unroll
        for (int ks = 0; ks < GBK; ks += 16) {
            uint32_t ah[2][4];
            #pragma unroll
            for (int i = 0; i < 2; i++) {
                int ra = (warp_m * 32 + i * 16 + a_row) * SA + ks + a_colh;
                ldmx4(ah[i], buf + OA + ra);
            }
            #pragma unroll
            for (int jp = 0; jp < 4; jp++) {
                int rb = (ks + b_row) * SB + warp_n * 64 + jp * 16 + b_colh;
                uint32_t th[4];
                ldmx4t(th, buf + OB + rb);
                uint32_t b0[2] = {th[0], th[1]}, b1[2] = {th[2], th[3]};
                #pragma unroll
                for (int i = 0; i < 2; i++) {
                    mma16816(acc[i][2 * jp],     ah[i], b0);
                    mma16816(acc[i][2 * jp + 1], ah[i], b1);
                }
            }
        }
    }

    #pragma unroll
    for (int i = 0; i < 2; i++) {
        #pragma unroll
        for (int j = 0; j < 8; j++) {
            int row0 = by * 128 + warp_m * 32 + i * 16 + g;
            int col  = bx * 128 + warp_n * 64 + j * 8 + tg * 2;
            float b0 = bias[col], b1 = bias[col + 1];
            float c00 = acc[i][j][0] + b0, c01 = acc[i][j][1] + b1;
            float c10 = acc[i][j][2] + b0, c11 = acc[i][j][3] + b1;
            if (OutHalf) {
                __half* C = reinterpret_cast<__half*>(Cv);
                *reinterpret_cast<__half2*>(C + (size_t)row0 * N + col) =
                    __floats2half2_rn(c00, c01);
                *reinterpret_cast<__half2*>(C + (size_t)(row0 + 8) * N + col) =
                    __floats2half2_rn(c10, c11);
            } else {
                float* C = reinterpret_cast<float*>(Cv);
                *reinterpret_cast<float2*>(C + (size_t)row0 * N + col) =
                    make_float2(c00, c01);
                *reinterpret_cast<float2*>(C + (size_t)(row0 + 8) * N + col) =
                    make_float2(c10, c11);
            }
        }
    }
}

// ---------------- RoPE + scatter (fp16 in/out) ----------------
__global__ __launch_bounds__(128) void qkv_rope_kernel(
    const __half* __restrict__ mixed,
    __half* __restrict__ Q, __half* __restrict__ K, __half* __restrict__ V)
{
    const int t = blockIdx.x;
    const int h = blockIdx.y;
    const int d = threadIdx.x;

    const __half* base = mixed + (size_t)t * NQKV + h * (3 * HD);
    float q = __half2float(base[d]);
    float k = __half2float(base[HD + d]);
    float v = __half2float(base[2 * HD + d]);

    if (d < ROT) {
        const int i = d & 15;
        float inv_freq = 1.0f / powf(10000.0f, (float)(2 * i) * (1.0f / (float)ROT));
        float ang = (float)t * inv_freq;
        float s, c;
        sincosf(ang, &s, &c);
        if (d < 16) {
            q = q * c - __half2float(base[d + 16]) * s;
            k = k * c - __half2float(base[HD + d + 16]) * s;
        } else {
            q = q * c + __half2float(base[d - 16]) * s;
            k = k * c + __half2float(base[HD + d - 16]) * s;
        }
    }

    size_t off = ((size_t)h * S_LEN + t) * HD + d;
    Q[off] = __float2half_rn(q);
    K[off] = __float2half_rn(k);
    V[off] = __float2half_rn(v);
}

// ---------------- HMMA flash attention (fp16, causal) ----------------
#define FBM 128
#define FBN 64
#define FSTR 136

#define FQ   0
#define FKV0 (128 * FSTR)            // 17408 halfs
#define KVARR (64 * FSTR)            // 8704 halfs per array
#define KVSTG (2 * KVARR)            // one stage: K, V
#define FLASH_SMEM ((FKV0 + 2 * KVSTG) * 2)   // 104448 B

__global__ __launch_bounds__(256, 1) void flash_mma_kernel(
    const __half* __restrict__ Q, const __half* __restrict__ K,
    const __half* __restrict__ V, __half* __restrict__ Cf)
{
    extern __shared__ __align__(16) unsigned char fsraw[];
    __half* fs = reinterpret_cast<__half*>(fsraw);

    const int h = blockIdx.y;
    const int m_tile = gridDim.x - 1 - blockIdx.x;
    const int m0 = m_tile * FBM;
    const int tid = threadIdx.x;
    const int warp = tid >> 5;
    const int lane = tid & 31;
    const int g  = lane >> 2;
    const int tg = lane & 3;

    const __half* qp = Q + ((size_t)h * S_LEN + m0) * HD;
    const __half* kp = K + (size_t)h * S_LEN * HD;
    const __half* vp = V + (size_t)h * S_LEN * HD;

    for (int idx = tid; idx < 2048; idx += 256) {
        int r = idx >> 4, c = (idx & 15) << 3;
        *reinterpret_cast<float4*>(fs + FQ + r * FSTR + c) =
            *reinterpret_cast<const float4*>(qp + (size_t)r * HD + c);
    }

    auto issue_kv = [&](int nt) {
        const int n0 = nt * FBN;
        __half* buf = fs + FKV0 + (nt & 1) * KVSTG;
        #pragma unroll
        for (int q = tid; q < 1024; q += 256) {
            int r = q >> 4, c = (q & 15) << 3;
            size_t go = (size_t)(n0 + r) * HD + c;
            int so = r * FSTR + c;
            cp_async16(buf + 0 * KVARR + so, kp + go);
            cp_async16(buf + 1 * KVARR + so, vp + go);
        }
    };

    float o[16][4];
    #pragma unroll
    for (int j = 0; j < 16; j++)
        #pragma unroll
        for (int x = 0; x < 4; x++) o[j][x] = 0.0f;
    float mrow0 = -1e30f, mrow1 = -1e30f, lrow0 = 0.0f, lrow1 = 0.0f;

    const float scale = 0.08838834764831845f;
    const int row0 = m0 + warp * 16 + g;
    const int row1 = row0 + 8;
    const int wrow_max = m0 + warp * 16 + 15;

    const int a_row = lane & 15;
    const int half8 = (lane >> 4) << 3;
    const int bk_colh = ((lane >> 3) & 1) << 3;

    const int ntiles = m0 / FBN + 2;
    issue_kv(0); cp_commit();

    for (int nt = 0; nt < ntiles; nt++) {
        const int n0 = nt * FBN;
        if (nt + 1 < ntiles) { issue_kv(nt + 1); cp_commit(); cp_wait<1>(); }
        else                 { cp_wait<0>(); }
        __syncthreads();

        if (n0 <= wrow_max) {
            const __half* kvb = fs + FKV0 + (nt & 1) * KVSTG;
            const __half* k_s = kvb;
            const __half* v_s = kvb + KVARR;

            float sacc[8][4];
            #pragma unroll
            for (int j = 0; j < 8; j++)
                #pragma unroll
                for (int x = 0; x < 4; x++) sacc[j][x] = 0.0f;

            #pragma unroll
            for (int ks = 0; ks < 8; ks++) {
                const int k = ks * 16;
                uint32_t aF[4];
                {
                    int ra = (warp * 16 + a_row) * FSTR + k + half8;
                    ldmx4(aF, fs + FQ + ra);
                }
                #pragma unroll
                for (int jp = 0; jp < 4; jp++) {
                    int rb = (jp * 16 + half8 + (lane & 7)) * FSTR + k + bk_colh;
                    uint32_t bF[4];
                    ldmx4(bF, k_s + rb);
                    uint32_t b0[2] = {bF[0], bF[1]}, b1[2] = {bF[2], bF[3]};
                    mma16816(sacc[2 * jp],     aF, b0);
                    mma16816(sacc[2 * jp + 1], aF, b1);
                }
            }

            const bool boundary = (n0 + FBN - 1 > m0);
            #pragma unroll
            for (int j = 0; j < 8; j++) {
                int c0 = n0 + j * 8 + 2 * tg;
                if (boundary) {
                    sacc[j][0] = (c0     > row0) ? -1e30f : sacc[j][0] * scale;
                    sacc[j][1] = (c0 + 1 > row0) ? -1e30f : sacc[j][1] * scale;
                    sacc[j][2] = (c0     > row1) ? -1e30f : sacc[j][2] * scale;
                    sacc[j][3] = (c0 + 1 > row1) ? -1e30f : sacc[j][3] * scale;
                } else {
                    sacc[j][0] *= scale; sacc[j][1] *= scale;
                    sacc[j][2] *= scale; sacc[j][3] *= scale;
                }
            }

            float mx0 = -1e30f, mx1 = -1e30f;
            #pragma unroll
            for (int j = 0; j < 8; j++) {
                mx0 = fmaxf(mx0, fmaxf(sacc[j][0], sacc[j][1]));
                mx1 = fmaxf(mx1, fmaxf(sacc[j][2], sacc[j][3]));
            }
            mx0 = fmaxf(mx0, __shfl_xor_sync(0xffffffffu, mx0, 1));
            mx0 = fmaxf(mx0, __shfl_xor_sync(0xffffffffu, mx0, 2));
            mx1 = fmaxf(mx1, __shfl_xor_sync(0xffffffffu, mx1, 1));
            mx1 = fmaxf(mx1, __shfl_xor_sync(0xffffffffu, mx1, 2));

            float mn0 = fmaxf(mrow0, mx0);
            float mn1 = fmaxf(mrow1, mx1);
            float alpha0 = __expf(mrow0 - mn0);
            float alpha1 = __expf(mrow1 - mn1);
            mrow0 = mn0; mrow1 = mn1;

            float sum0 = 0.0f, sum1 = 0.0f;
            #pragma unroll
            for (int j = 0; j < 8; j++) {
                sacc[j][0] = __expf(sacc[j][0] - mn0);
                sacc[j][1] = __expf(sacc[j][1] - mn0);
                sacc[j][2] = __expf(sacc[j][2] - mn1);
                sacc[j][3] = __expf(sacc[j][3] - mn1);
                sum0 += sacc[j][0] + sacc[j][1];
                sum1 += sacc[j][2] + sacc[j][3];
            }
            sum0 += __shfl_xor_sync(0xffffffffu, sum0, 1);
            sum0 += __shfl_xor_sync(0xffffffffu, sum0, 2);
            sum1 += __shfl_xor_sync(0xffffffffu, sum1, 1);
            sum1 += __shfl_xor_sync(0xffffffffu, sum1, 2);
            lrow0 = lrow0 * alpha0 + sum0;
            lrow1 = lrow1 * alpha1 + sum1;

            #pragma unroll
            for (int j = 0; j < 16; j++) {
                o[j][0] *= alpha0; o[j][1] *= alpha0;
                o[j][2] *= alpha1; o[j][3] *= alpha1;
            }

            #pragma unroll
            for (int kk = 0; kk < 4; kk++) {
                uint32_t pa[4];
                #pragma unroll
                for (int half = 0; half < 2; half++) {
                    const float* sv = sacc[2 * kk + half];
                    __half2 h0 = __floats2half2_rn(sv[0], sv[1]);
                    __half2 h1 = __floats2half2_rn(sv[2], sv[3]);
                    pa[2 * half]     = *reinterpret_cast<uint32_t*>(&h0);
                    pa[2 * half + 1] = *reinterpret_cast<uint32_t*>(&h1);
                }
                #pragma unroll
                for (int jp = 0; jp < 8; jp++) {
                    int rv = (kk * 16 + a_row) * FSTR + jp * 16 + half8;
                    uint32_t vF[4];
                    ldmx4t(vF, v_s + rv);
                    uint32_t v0[2] = {vF[0], vF[1]}, v1[2] = {vF[2], vF[3]};
                    mma16816(o[2 * jp],     pa, v0);
                    mma16816(o[2 * jp + 1], pa, v1);
                }
            }
        }
        __syncthreads();
    }

    float inv0 = 1.0f / lrow0;
    float inv1 = 1.0f / lrow1;
    #pragma unroll
    for (int jt = 0; jt < 16; jt++) {
        int col = h * HD + jt * 8 + 2 * tg;
        __half2 r0 = __floats2half2_rn(o[jt][0] * inv0, o[jt][1] * inv0);
        __half2 r1 = __floats2half2_rn(o[jt][2] * inv1, o[jt][3] * inv1);
        *reinterpret_cast<__half2*>(Cf + (size_t)row0 * HID + col) = r0;
        *reinterpret_cast<__half2*>(Cf + (size_t)row1 * HID + col) = r1;
    }
}

// ---------------- launch ----------------
extern "C" void kernel_launch(void* const* d_in, const int* in_sizes, int n_in,
                              void* d_out, int out_size)
{
    const float* hidden  = (const float*)d_in[0];
    const float* W_qkv   = (const float*)d_in[1];
    const float* b_qkv   = (const float*)d_in[2];
    const float* W_dense = (const float*)d_in[3];
    const float* b_dense = (const float*)d_in[4];
    float* out = (float*)d_out;

    __half *mixed, *a, *b, *w, *c, *qf, *kf, *vf;
    cudaGetSymbolAddress((void**)&mixed, g_mixed);
    cudaGetSymbolAddress((void**)&a,  g_a);
    cudaGetSymbolAddress((void**)&b,  g_b);
    cudaGetSymbolAddress((void**)&w,  g_w);
    cudaGetSymbolAddress((void**)&c,  g_c);
    cudaGetSymbolAddress((void**)&qf, g_qf);
    cudaGetSymbolAddress((void**)&kf, g_kf);
    cudaGetSymbolAddress((void**)&vf, g_vf);

    cudaFuncSetAttribute(mma_gemm_fp16<true>,
                         cudaFuncAttributeMaxDynamicSharedMemorySize, GEMM_SMEM);
    cudaFuncSetAttribute(mma_gemm_fp16<false>,
                         cudaFuncAttributeMaxDynamicSharedMemorySize, GEMM_SMEM);
    cudaFuncSetAttribute(flash_mma_kernel,
                         cudaFuncAttributeMaxDynamicSharedMemorySize, FLASH_SMEM);

    // 0) fp16 conversions
    {
        int n4 = S_LEN * HID / 4;
        to_fp16_kernel<<<(n4 + 255) / 256, 256>>>(hidden, a, n4);
        int w4 = HID * NQKV / 4;
        to_fp16_kernel<<<(w4 + 255) / 256, 256>>>(W_qkv, b, w4);
        int d4 = HID * HID / 4;
        to_fp16_kernel<<<(d4 + 255) / 256, 256>>>(W_dense, w, d4);
    }

    // 1) QKV projection (+bias) -> fp16 mixed
    {
        dim3 grid(NQKV / 128, S_LEN / 128);
        mma_gemm_fp16<true><<<grid, 256, GEMM_SMEM>>>(a, b, b_qkv, mixed,
                                                      S_LEN, NQKV, HID);
    }

    // 2) RoPE + scatter (fp16)
    qkv_rope_kernel<<<dim3(S_LEN, NH), 128>>>(mixed, qf, kf, vf);

    // 3) causal flash attention (fp16); writes ctx fp16
    flash_mma_kernel<<<dim3(S_LEN / FBM, NH), 256, FLASH_SMEM>>>(qf, kf, vf, c);

    // 4) dense projection (+bias) -> fp32 out
    {
        dim3 grid(HID / 128, S_LEN / 128);
        mma_gemm_fp16<false><<<grid, 256, GEMM_SMEM>>>(c, w, b_dense, out,
                                                       S_LEN, HID, HID);
    }
}

// round 14
// speedup vs baseline: 2.4834x; 1.0766x over previous
#include <cuda_runtime.h>
#include <cuda_fp16.h>
#include <cstdint>
#include <math.h>

using std::uint32_t;

// ---------------- problem constants ----------------
#define S_LEN 2048
#define HID   2048
#define NH    16
#define HD    128
#define NQKV  6144   // 3 * HID
#define ROT   32

// ---------------- scratch (device globals; no runtime alloc) ----------------
__device__ __half g_a[(size_t)S_LEN * HID];     // hidden fp16
__device__ __half g_b[(size_t)HID * NQKV];      // W_qkv fp16
__device__ __half g_w[(size_t)HID * HID];       // W_dense fp16
__device__ __half g_c[(size_t)S_LEN * HID];     // ctx fp16 (written by flash)

__device__ __half g_qf[(size_t)NH * S_LEN * HD];   // pre-scaled, roped
__device__ __half g_kf[(size_t)NH * S_LEN * HD];   // roped
__device__ __half g_vf[(size_t)NH * S_LEN * HD];

// ---------------- common PTX helpers ----------------
__device__ __forceinline__ void cp_async16(void* smem_dst, const void* gmem_src) {
    uint32_t s = (uint32_t)__cvta_generic_to_shared(smem_dst);
    asm volatile("cp.async.cg.shared.global [%0], [%1], 16;\n" :: "r"(s), "l"(gmem_src));
}
__device__ __forceinline__ void cp_commit() {
    asm volatile("cp.async.commit_group;\n");
}
template <int N>
__device__ __forceinline__ void cp_wait() {
    asm volatile("cp.async.wait_group %0;\n" :: "n"(N));
}

__device__ __forceinline__ void mma16816(float* c, const uint32_t* a, const uint32_t* b) {
    asm volatile(
        "mma.sync.aligned.m16n8k16.row.col.f32.f16.f16.f32 "
        "{%0,%1,%2,%3}, {%4,%5,%6,%7}, {%8,%9}, {%0,%1,%2,%3};\n"
        : "+f"(c[0]), "+f"(c[1]), "+f"(c[2]), "+f"(c[3])
        : "r"(a[0]), "r"(a[1]), "r"(a[2]), "r"(a[3]), "r"(b[0]), "r"(b[1]));
}

__device__ __forceinline__ void ldmx4(uint32_t* r, const void* p) {
    uint32_t a = (uint32_t)__cvta_generic_to_shared(p);
    asm volatile("ldmatrix.sync.aligned.m8n8.x4.shared.b16 {%0,%1,%2,%3}, [%4];"
                 : "=r"(r[0]), "=r"(r[1]), "=r"(r[2]), "=r"(r[3]) : "r"(a));
}
__device__ __forceinline__ void ldmx4t(uint32_t* r, const void* p) {
    uint32_t a = (uint32_t)__cvta_generic_to_shared(p);
    asm volatile("ldmatrix.sync.aligned.m8n8.x4.trans.shared.b16 {%0,%1,%2,%3}, [%4];"
                 : "=r"(r[0]), "=r"(r[1]), "=r"(r[2]), "=r"(r[3]) : "r"(a));
}

// ---------------- fp32 -> fp16 convert ----------------
__global__ __launch_bounds__(256) void to_fp16_kernel(
    const float* __restrict__ x, __half* __restrict__ y, int n4)
{
    int i = blockIdx.x * blockDim.x + threadIdx.x;
    if (i >= n4) return;
    float4 v = reinterpret_cast<const float4*>(x)[i];
    __half2* yp = reinterpret_cast<__half2*>(y);
    yp[2 * i]     = __floats2half2_rn(v.x, v.y);
    yp[2 * i + 1] = __floats2half2_rn(v.z, v.w);
}

// ---------------- GEMM tiling constants ----------------
#define GBK 64
#define SA     72                    // 64 + 8 pad (halfs)
#define SB     136                   // 128 + 8 pad
#define OA     0
#define OB     (128 * SA)            // 9216
#define BUFSZ  (OB + GBK * SB)       // 17920 halfs = 35840 B
#define GEMM_SMEM (3 * BUFSZ * 2)    // 107520 B

// ---------------- main-loop macro body shared by both GEMMs ----------------
// (identical structure: 128x128 tile, BK=64, 256 thr 4x2 warps, 3-stage ring)

// ---------------- QKV GEMM + bias + RoPE + head-major scatter ----------------
__global__ __launch_bounds__(256, 2) void qkv_gemm_rope(
    const __half* __restrict__ A, const __half* __restrict__ B,
    const float* __restrict__ bias,
    __half* __restrict__ Qp, __half* __restrict__ Kp, __half* __restrict__ Vp)
{
    extern __shared__ __align__(16) unsigned char smraw[];
    __half* sm = reinterpret_cast<__half*>(smraw);

    const int bx = blockIdx.x;     // N tile: maps to (head, sel)
    const int by = blockIdx.y;     // M tile (sequence)
    const int tid = threadIdx.x;
    const int warp = tid >> 5;
    const int lane = tid & 31;
    const int warp_m = warp & 3;
    const int warp_n = warp >> 2;
    const int g  = lane >> 2;
    const int tg = lane & 3;
    const int K = HID, N = NQKV;
    const int nst = K / GBK;

    float acc[2][8][4];
    #pragma unroll
    for (int i = 0; i < 2; i++)
        #pragma unroll
        for (int j = 0; j < 8; j++)
            #pragma unroll
            for (int x = 0; x < 4; x++) acc[i][j][x] = 0.0f;

    auto issue = [&](int s) {
        const int k0 = s * GBK;
        __half* buf = sm + (s % 3) * BUFSZ;
        #pragma unroll
        for (int p = 0; p < 4; p++) {
            int q = tid + p * 256;
            int r = q >> 3, c = q & 7;
            size_t ga = (size_t)(by * 128 + r) * K + k0 + c * 8;
            cp_async16(buf + OA + r * SA + c * 8, A + ga);
        }
        #pragma unroll
        for (int p = 0; p < 4; p++) {
            int q = tid + p * 256;
            int r = q >> 4, c = q & 15;
            size_t gb = (size_t)(k0 + r) * N + bx * 128 + c * 8;
            cp_async16(buf + OB + r * SB + c * 8, B + gb);
        }
    };

    issue(0); cp_commit();
    issue(1); cp_commit();

    const int a_row = lane & 15;
    const int a_colh = (lane >> 4) << 3;
    const int b_row = lane & 15;
    const int b_colh = (lane >> 4) << 3;

    for (int s = 0; s < nst; s++) {
        cp_wait<1>();
        __syncthreads();
        if (s + 2 < nst) { issue(s + 2); cp_commit(); }

        const __half* buf = sm + (s % 3) * BUFSZ;

        #pragma unroll
        for (int ks = 0; ks < GBK; ks += 16) {
            uint32_t ah[2][4];
            #pragma unroll
            for (int i = 0; i < 2; i++) {
                int ra = (warp_m * 32 + i * 16 + a_row) * SA + ks + a_colh;
                ldmx4(ah[i], buf + OA + ra);
            }
            #pragma unroll
            for (int jp = 0; jp < 4; jp++) {
                int rb = (ks + b_row) * SB + warp_n * 64 + jp * 16 + b_colh;
                uint32_t th[4];
                ldmx4t(th, buf + OB + rb);
                uint32_t b0[2] = {th[0], th[1]}, b1[2] = {th[2], th[3]};
                #pragma unroll
                for (int i = 0; i < 2; i++) {
                    mma16816(acc[i][2 * jp],     ah[i], b0);
                    mma16816(acc[i][2 * jp + 1], ah[i], b1);
                }
            }
        }
    }

    // ---- epilogue: bias, RoPE (q/k), scale (q), head-major scatter ----
    const int head = bx / 3;
    const int sel  = bx - head * 3;      // 0=q, 1=k, 2=v
    __half* dst = (sel == 0) ? Qp : (sel == 1) ? Kp : Vp;
    const float qscale = 0.08838834764831845f;  // 1/sqrt(128)

    // bias add
    #pragma unroll
    for (int i = 0; i < 2; i++)
        #pragma unroll
        for (int j = 0; j < 8; j++) {
            int col = bx * 128 + warp_n * 64 + j * 8 + tg * 2;
            float b0 = bias[col], b1 = bias[col + 1];
            acc[i][j][0] += b0; acc[i][j][1] += b1;
            acc[i][j][2] += b0; acc[i][j][3] += b1;
        }

    // RoPE on first 32 dims (pairs d, d+16 live in j and j+2)
    if (sel < 2 && warp_n == 0) {
        #pragma unroll
        for (int i = 0; i < 2; i++) {
            int r0 = by * 128 + warp_m * 32 + i * 16 + g;
            #pragma unroll
            for (int j = 0; j < 2; j++) {
                #pragma unroll
                for (int e = 0; e < 2; e++) {
                    int d = j * 8 + tg * 2 + e;            // < 16
                    float invf = powf(10000.0f, -(float)(2 * d) / 32.0f);
                    float s0, c0, s1, c1;
                    sincosf((float)r0 * invf, &s0, &c0);
                    sincosf((float)(r0 + 8) * invf, &s1, &c1);
                    float x1a = acc[i][j][e],     x2a = acc[i][j + 2][e];
                    float x1b = acc[i][j][e + 2], x2b = acc[i][j + 2][e + 2];
                    acc[i][j][e]         = x1a * c0 - x2a * s0;
                    acc[i][j + 2][e]     = x2a * c0 + x1a * s0;
                    acc[i][j][e + 2]     = x1b * c1 - x2b * s1;
                    acc[i][j + 2][e + 2] = x2b * c1 + x1b * s1;
                }
            }
        }
    }

    // scale q (fold 1/sqrt(hd))
    if (sel == 0) {
        #pragma unroll
        for (int i = 0; i < 2; i++)
            #pragma unroll
            for (int j = 0; j < 8; j++)
                #pragma unroll
                for (int x = 0; x < 4; x++) acc[i][j][x] *= qscale;
    }

    // scatter head-major fp16
    #pragma unroll
    for (int i = 0; i < 2; i++) {
        int row0 = by * 128 + warp_m * 32 + i * 16 + g;
        #pragma unroll
        for (int j = 0; j < 8; j++) {
            int d = warp_n * 64 + j * 8 + tg * 2;
            size_t o0 = ((size_t)head * S_LEN + row0) * HD + d;
            size_t o1 = ((size_t)head * S_LEN + row0 + 8) * HD + d;
            *reinterpret_cast<__half2*>(dst + o0) =
                __floats2half2_rn(acc[i][j][0], acc[i][j][1]);
            *reinterpret_cast<__half2*>(dst + o1) =
                __floats2half2_rn(acc[i][j][2], acc[i][j][3]);
        }
    }
}

// ---------------- dense GEMM (fp16 in, fp32 out + bias) ----------------
__global__ __launch_bounds__(256, 2) void mma_gemm_dense(
    const __half* __restrict__ A, const __half* __restrict__ B,
    const float* __restrict__ bias, float* __restrict__ C)
{
    extern __shared__ __align__(16) unsigned char smraw[];
    __half* sm = reinterpret_cast<__half*>(smraw);

    const int bx = blockIdx.x;
    const int by = blockIdx.y;
    const int tid = threadIdx.x;
    const int warp = tid >> 5;
    const int lane = tid & 31;
    const int warp_m = warp & 3;
    const int warp_n = warp >> 2;
    const int g  = lane >> 2;
    const int tg = lane & 3;
    const int K = HID, N = HID;
    const int nst = K / GBK;

    float acc[2][8][4];
    #pragma unroll
    for (int i = 0; i < 2; i++)
        #pragma unroll
        for (int j = 0; j < 8; j++)
            #pragma unroll
            for (int x = 0; x < 4; x++) acc[i][j][x] = 0.0f;

    auto issue = [&](int s) {
        const int k0 = s * GBK;
        __half* buf = sm + (s % 3) * BUFSZ;
        #pragma unroll
        for (int p = 0; p < 4; p++) {
            int q = tid + p * 256;
            int r = q >> 3, c = q & 7;
            size_t ga = (size_t)(by * 128 + r) * K + k0 + c * 8;
            cp_async16(buf + OA + r * SA + c * 8, A + ga);
        }
        #pragma unroll
        for (int p = 0; p < 4; p++) {
            int q = tid + p * 256;
            int r = q >> 4, c = q & 15;
            size_t gb = (size_t)(k0 + r) * N + bx * 128 + c * 8;
            cp_async16(buf + OB + r * SB + c * 8, B + gb);
        }
    };

    issue(0); cp_commit();
    issue(1); cp_commit();

    const int a_row = lane & 15;
    const int a_colh = (lane >> 4) << 3;
    const int b_row = lane & 15;
    const int b_colh = (lane >> 4) << 3;

    for (int s = 0; s < nst; s++) {
        cp_wait<1>();
        __syncthreads();
        if (s + 2 < nst) { issue(s + 2); cp_commit(); }

        const __half* buf = sm + (s % 3) * BUFSZ;

        #pragma unroll
        for (int ks = 0; ks < GBK; ks += 16) {
            uint32_t ah[2][4];
            #pragma unroll
            for (int i = 0; i < 2; i++) {
                int ra = (warp_m * 32 + i * 16 + a_row) * SA + ks + a_colh;
                ldmx4(ah[i], buf + OA + ra);
            }
            #pragma unroll
            for (int jp = 0; jp < 4; jp++) {
                int rb = (ks + b_row) * SB + warp_n * 64 + jp * 16 + b_colh;
                uint32_t th[4];
                ldmx4t(th, buf + OB + rb);
                uint32_t b0[2] = {th[0], th[1]}, b1[2] = {th[2], th[3]};
                #pragma unroll
                for (int i = 0; i < 2; i++) {
                    mma16816(acc[i][2 * jp],     ah[i], b0);
                    mma16816(acc[i][2 * jp + 1], ah[i], b1);
                }
            }
        }
    }

    #pragma unroll
    for (int i = 0; i < 2; i++) {
        #pragma unroll
        for (int j = 0; j < 8; j++) {
            int row0 = by * 128 + warp_m * 32 + i * 16 + g;
            int col  = bx * 128 + warp_n * 64 + j * 8 + tg * 2;
            float b0 = bias[col], b1 = bias[col + 1];
            *reinterpret_cast<float2*>(C + (size_t)row0 * N + col) =
                make_float2(acc[i][j][0] + b0, acc[i][j][1] + b1);
            *reinterpret_cast<float2*>(C + (size_t)(row0 + 8) * N + col) =
                make_float2(acc[i][j][2] + b0, acc[i][j][3] + b1);
        }
    }
}

// ---------------- HMMA flash attention (fp16, causal, FBN=128) ----------------
#define FBM 128
#define FBN 128
#define FSTR 136

#define FQ   0
#define FKV0 (128 * FSTR)            // 17408 halfs
#define KVARR (128 * FSTR)           // 17408 halfs per array
#define KVSTG (2 * KVARR)            // one stage: K, V
#define FLASH_SMEM ((FKV0 + 2 * KVSTG) * 2)   // 174080 B

__global__ __launch_bounds__(256, 1) void flash_mma_kernel(
    const __half* __restrict__ Q, const __half* __restrict__ K,
    const __half* __restrict__ V, __half* __restrict__ Cf)
{
    extern __shared__ __align__(16) unsigned char fsraw[];
    __half* fs = reinterpret_cast<__half*>(fsraw);

    const int h = blockIdx.y;
    const int m_tile = gridDim.x - 1 - blockIdx.x;
    const int m0 = m_tile * FBM;
    const int tid = threadIdx.x;
    const int warp = tid >> 5;
    const int lane = tid & 31;
    const int g  = lane >> 2;
    const int tg = lane & 3;

    const __half* qp = Q + ((size_t)h * S_LEN + m0) * HD;
    const __half* kp = K + (size_t)h * S_LEN * HD;
    const __half* vp = V + (size_t)h * S_LEN * HD;

    for (int idx = tid; idx < 2048; idx += 256) {
        int r = idx >> 4, c = (idx & 15) << 3;
        *reinterpret_cast<float4*>(fs + FQ + r * FSTR + c) =
            *reinterpret_cast<const float4*>(qp + (size_t)r * HD + c);
    }

    auto issue_kv = [&](int nt) {
        const int n0 = nt * FBN;
        __half* buf = fs + FKV0 + (nt & 1) * KVSTG;
        #pragma unroll
        for (int q = tid; q < 2048; q += 256) {
            int r = q >> 4, c = (q & 15) << 3;
            size_t go = (size_t)(n0 + r) * HD + c;
            int so = r * FSTR + c;
            cp_async16(buf + 0 * KVARR + so, kp + go);
            cp_async16(buf + 1 * KVARR + so, vp + go);
        }
    };

    float o[16][4];
    #pragma unroll
    for (int j = 0; j < 16; j++)
        #pragma unroll
        for (int x = 0; x < 4; x++) o[j][x] = 0.0f;
    float mrow0 = -1e30f, mrow1 = -1e30f, lrow0 = 0.0f, lrow1 = 0.0f;

    const int row0 = m0 + warp * 16 + g;
    const int row1 = row0 + 8;

    const int a_row = lane & 15;
    const int half8 = (lane >> 4) << 3;
    const int bk_colh = ((lane >> 3) & 1) << 3;

    const int ntiles = m0 / FBN + 1;
    issue_kv(0); cp_commit();

    for (int nt = 0; nt < ntiles; nt++) {
        const int n0 = nt * FBN;
        if (nt + 1 < ntiles) { issue_kv(nt + 1); cp_commit(); cp_wait<1>(); }
        else                 { cp_wait<0>(); }
        __syncthreads();

        const __half* kvb = fs + FKV0 + (nt & 1) * KVSTG;
        const __half* k_s = kvb;
        const __half* v_s = kvb + KVARR;

        float sacc[16][4];
        #pragma unroll
        for (int j = 0; j < 16; j++)
            #pragma unroll
            for (int x = 0; x < 4; x++) sacc[j][x] = 0.0f;

        #pragma unroll
        for (int ks = 0; ks < 8; ks++) {
            const int k = ks * 16;
            uint32_t aF[4];
            {
                int ra = (warp * 16 + a_row) * FSTR + k + half8;
                ldmx4(aF, fs + FQ + ra);
            }
            #pragma unroll
            for (int jp = 0; jp < 8; jp++) {
                int rb = (jp * 16 + half8 + (lane & 7)) * FSTR + k + bk_colh;
                uint32_t bF[4];
                ldmx4(bF, k_s + rb);
                uint32_t b0[2] = {bF[0], bF[1]}, b1[2] = {bF[2], bF[3]};
                mma16816(sacc[2 * jp],     aF, b0);
                mma16816(sacc[2 * jp + 1], aF, b1);
            }
        }

        // causal mask (Q pre-scaled; only last tile is boundary)
        if (nt == ntiles - 1) {
            #pragma unroll
            for (int j = 0; j < 16; j++) {
                int c0 = n0 + j * 8 + 2 * tg;
                if (c0     > row0) sacc[j][0] = -1e30f;
                if (c0 + 1 > row0) sacc[j][1] = -1e30f;
                if (c0     > row1) sacc[j][2] = -1e30f;
                if (c0 + 1 > row1) sacc[j][3] = -1e30f;
            }
        }

        float mx0 = -1e30f, mx1 = -1e30f;
        #pragma unroll
        for (int j = 0; j < 16; j++) {
            mx0 = fmaxf(mx0, fmaxf(sacc[j][0], sacc[j][1]));
            mx1 = fmaxf(mx1, fmaxf(sacc[j][2], sacc[j][3]));
        }
        mx0 = fmaxf(mx0, __shfl_xor_sync(0xffffffffu, mx0, 1));
        mx0 = fmaxf(mx0, __shfl_xor_sync(0xffffffffu, mx0, 2));
        mx1 = fmaxf(mx1, __shfl_xor_sync(0xffffffffu, mx1, 1));
        mx1 = fmaxf(mx1, __shfl_xor_sync(0xffffffffu, mx1, 2));

        float mn0 = fmaxf(mrow0, mx0);
        float mn1 = fmaxf(mrow1, mx1);
        float alpha0 = __expf(mrow0 - mn0);
        float alpha1 = __expf(mrow1 - mn1);
        mrow0 = mn0; mrow1 = mn1;

        float sum0 = 0.0f, sum1 = 0.0f;
        #pragma unroll
        for (int j = 0; j < 16; j++) {
            sacc[j][0] = __expf(sacc[j][0] - mn0);
            sacc[j][1] = __expf(sacc[j][1] - mn0);
            sacc[j][2] = __expf(sacc[j][2] - mn1);
            sacc[j][3] = __expf(sacc[j][3] - mn1);
            sum0 += sacc[j][0] + sacc[j][1];
            sum1 += sacc[j][2] + sacc[j][3];
        }
        sum0 += __shfl_xor_sync(0xffffffffu, sum0, 1);
        sum0 += __shfl_xor_sync(0xffffffffu, sum0, 2);
        sum1 += __shfl_xor_sync(0xffffffffu, sum1, 1);
        sum1 += __shfl_xor_sync(0xffffffffu, sum1, 2);
        lrow0 = lrow0 * alpha0 + sum0;
        lrow1 = lrow1 * alpha1 + sum1;

        #pragma unroll
        for (int j = 0; j < 16; j++) {
            o[j][0] *= alpha0; o[j][1] *= alpha0;
            o[j][2] *= alpha1; o[j][3] *= alpha1;
        }

        #pragma unroll
        for (int kk = 0; kk < 8; kk++) {
            uint32_t pa[4];
            #pragma unroll
            for (int half = 0; half < 2; half++) {
                const float* sv = sacc[2 * kk + half];
                __half2 h0 = __floats2half2_rn(sv[0], sv[1]);
                __half2 h1 = __floats2half2_rn(sv[2], sv[3]);
                pa[2 * half]     = *reinterpret_cast<uint32_t*>(&h0);
                pa[2 * half + 1] = *reinterpret_cast<uint32_t*>(&h1);
            }
            #pragma unroll
            for (int jp = 0; jp < 8; jp++) {
                int rv = (kk * 16 + a_row) * FSTR + jp * 16 + half8;
                uint32_t vF[4];
                ldmx4t(vF, v_s + rv);
                uint32_t v0[2] = {vF[0], vF[1]}, v1[2] = {vF[2], vF[3]};
                mma16816(o[2 * jp],     pa, v0);
                mma16816(o[2 * jp + 1], pa, v1);
            }
        }
        __syncthreads();
    }

    float inv0 = 1.0f / lrow0;
    float inv1 = 1.0f / lrow1;
    #pragma unroll
    for (int jt = 0; jt < 16; jt++) {
        int col = h * HD + jt * 8 + 2 * tg;
        __half2 r0 = __floats2half2_rn(o[jt][0] * inv0, o[jt][1] * inv0);
        __half2 r1 = __floats2half2_rn(o[jt][2] * inv1, o[jt][3] * inv1);
        *reinterpret_cast<__half2*>(Cf + (size_t)row0 * HID + col) = r0;
        *reinterpret_cast<__half2*>(Cf + (size_t)row1 * HID + col) = r1;
    }
}

// ---------------- launch ----------------
extern "C" void kernel_launch(void* const* d_in, const int* in_sizes, int n_in,
                              void* d_out, int out_size)
{
    const float* hidden  = (const float*)d_in[0];
    const float* W_qkv   = (const float*)d_in[1];
    const float* b_qkv   = (const float*)d_in[2];
    const float* W_dense = (const float*)d_in[3];
    const float* b_dense = (const float*)d_in[4];
    float* out = (float*)d_out;

    __half *a, *b, *w, *c, *qf, *kf, *vf;
    cudaGetSymbolAddress((void**)&a,  g_a);
    cudaGetSymbolAddress((void**)&b,  g_b);
    cudaGetSymbolAddress((void**)&w,  g_w);
    cudaGetSymbolAddress((void**)&c,  g_c);
    cudaGetSymbolAddress((void**)&qf, g_qf);
    cudaGetSymbolAddress((void**)&kf, g_kf);
    cudaGetSymbolAddress((void**)&vf, g_vf);

    cudaFuncSetAttribute(qkv_gemm_rope,
                         cudaFuncAttributeMaxDynamicSharedMemorySize, GEMM_SMEM);
    cudaFuncSetAttribute(mma_gemm_dense,
                         cudaFuncAttributeMaxDynamicSharedMemorySize, GEMM_SMEM);
    cudaFuncSetAttribute(flash_mma_kernel,
                         cudaFuncAttributeMaxDynamicSharedMemorySize, FLASH_SMEM);

    // 0) fp16 conversions
    {
        int n4 = S_LEN * HID / 4;
        to_fp16_kernel<<<(n4 + 255) / 256, 256>>>(hidden, a, n4);
        int w4 = HID * NQKV / 4;
        to_fp16_kernel<<<(w4 + 255) / 256, 256>>>(W_qkv, b, w4);
        int d4 = HID * HID / 4;
        to_fp16_kernel<<<(d4 + 255) / 256, 256>>>(W_dense, w, d4);
    }

    // 1) QKV projection + bias + RoPE + scatter (head-major, q pre-scaled)
    {
        dim3 grid(NQKV / 128, S_LEN / 128);
        qkv_gemm_rope<<<grid, 256, GEMM_SMEM>>>(a, b, b_qkv, qf, kf, vf);
    }

    // 2) causal flash attention (fp16); writes ctx fp16
    flash_mma_kernel<<<dim3(S_LEN / FBM, NH), 256, FLASH_SMEM>>>(qf, kf, vf, c);

    // 3) dense projection (+bias) -> fp32 out
    {
        dim3 grid(HID / 128, S_LEN / 128);
        mma_gemm_dense<<<grid, 256, GEMM_SMEM>>>(c, w, b_dense, out);
    }
}